// round 9
// baseline (speedup 1.0000x reference)
#include <cuda_runtime.h>
#include <cuda_bf16.h>
#include <stdint.h>

#define NB 4
#define NC 256
#define NO 256
#define NL 4096          // H*W
#define NEPS 1e-5f
#define LOG2E 1.4426950408889634f

#define ATT_THREADS 1024
// smem floats: t12 8712 (66x66 float2) | xs 4356 | w 36864 = 49932 floats (199728 B)
#define ATT_F_T12  0
#define ATT_F_XS   8712
#define ATT_F_W    (8712 + 4356)
#define ATT_SMEM_BYTES ((8712 + 4356 + 36864) * 4)

#define EX2_APPROX(d, a) \
    asm("ex2.approx.ftz.f32 %0, %1;" : "=f"(d) : "f"(a))

// ---- tensor-core helpers (canonical m16n8k16 bf16 fragments) ----
#define LDSM_X4(r, a) \
    asm volatile("ldmatrix.sync.aligned.m8n8.x4.shared.b16 {%0,%1,%2,%3}, [%4];" \
        : "=r"((r)[0]), "=r"((r)[1]), "=r"((r)[2]), "=r"((r)[3]) : "r"(a))
#define LDSM_X4_T(r, a) \
    asm volatile("ldmatrix.sync.aligned.m8n8.x4.trans.shared.b16 {%0,%1,%2,%3}, [%4];" \
        : "=r"((r)[0]), "=r"((r)[1]), "=r"((r)[2]), "=r"((r)[3]) : "r"(a))
#define MMA_BF16(c, a, b0_, b1_) \
    asm volatile("mma.sync.aligned.m16n8k16.row.col.f32.bf16.bf16.f32 " \
        "{%0,%1,%2,%3}, {%4,%5,%6,%7}, {%8,%9}, {%0,%1,%2,%3};" \
        : "+f"((c)[0]), "+f"((c)[1]), "+f"((c)[2]), "+f"((c)[3]) \
        : "r"((a)[0]), "r"((a)[1]), "r"((a)[2]), "r"((a)[3]), "r"(b0_), "r"(b1_))

__device__ __forceinline__ uint32_t cvta_smem(const void* p) {
    return (uint32_t)__cvta_generic_to_shared(p);
}

// ---------------- scratch (static device globals; no runtime allocs) ----------------
static __device__ float g_y1[NB*NC*NL];
static __device__ float g_y2[NB*NC*NL];
static __device__ __nv_bfloat16 g_xh[NB*NC*NL],  g_xl[NB*NC*NL];
static __device__ __nv_bfloat16 g_ph[NB*NC*NL],  g_pl[NB*NC*NL];
static __device__ __nv_bfloat16 g_wh[2*NC*NC],   g_wl[2*NC*NC];     // w1 | w2 stacked
static __device__ __nv_bfloat16 g_wfh[NO*NC],    g_wfl[NO*NC];
static __device__ float g_sc1[NC], g_sh1[NC];
static __device__ float g_sc2[NC], g_sh2[NC];

// ---------------- fp32 -> bf16 hi/lo conversion (x and all weights, one launch) -----
__device__ __forceinline__ void split2(const float a, const float b,
                                       __nv_bfloat162* dh, __nv_bfloat162* dl)
{
    __nv_bfloat16 ha = __float2bfloat16(a), hb = __float2bfloat16(b);
    __nv_bfloat16 la = __float2bfloat16(a - __bfloat162float(ha));
    __nv_bfloat16 lb = __float2bfloat16(b - __bfloat162float(hb));
    *dh = __halves2bfloat162(ha, hb);
    *dl = __halves2bfloat162(la, lb);
}

#define CONV_X_BLOCKS ((NB*NC*NL) / (256 * 4))      // 16384
#define CONV_W_BLOCKS ((3*NC*NC) / (256 * 4))       // 192

__global__ __launch_bounds__(256) void conv_all_kernel(
    const float* __restrict__ x,
    const float* __restrict__ w1, const float* __restrict__ w2,
    const float* __restrict__ wf)
{
    if (blockIdx.x < CONV_X_BLOCKS) {
        const int i = (blockIdx.x * 256 + threadIdx.x) * 4;
        float4 v = *(const float4*)&x[i];
        split2(v.x, v.y, (__nv_bfloat162*)&g_xh[i],     (__nv_bfloat162*)&g_xl[i]);
        split2(v.z, v.w, (__nv_bfloat162*)&g_xh[i + 2], (__nv_bfloat162*)&g_xl[i + 2]);
    } else {
        const int i = ((blockIdx.x - CONV_X_BLOCKS) * 256 + threadIdx.x) * 4;
        float4 v;
        __nv_bfloat162 *dh, *dl;
        if (i < 65536)       { v = *(const float4*)&w1[i];          dh = (__nv_bfloat162*)&g_wh[i];  dl = (__nv_bfloat162*)&g_wl[i]; }
        else if (i < 131072) { v = *(const float4*)&w2[i - 65536];  dh = (__nv_bfloat162*)&g_wh[i];  dl = (__nv_bfloat162*)&g_wl[i]; }
        else                 { v = *(const float4*)&wf[i - 131072]; dh = (__nv_bfloat162*)&g_wfh[i - 131072]; dl = (__nv_bfloat162*)&g_wfl[i - 131072]; }
        split2(v.x, v.y, dh,     dl);
        split2(v.z, v.w, dh + 1, dl + 1);
    }
}

// ---------------- bf16x3 tensor-core GEMM (pre-split, smem double-buffered) ---------
#define APAD 40
#define BPAD 136
#define A_ELT (128 * APAD)     // 5120 bf16 per A buffer
#define B_ELT (32 * BPAD)      // 4352 bf16 per B buffer
#define GEMM_SMEM_BYTES ((2 * A_ELT * 2 + 2 * B_ELT * 2) * 2)   // 75776 B

__global__ __launch_bounds__(256) void mma_gemm_kernel(
    const __nv_bfloat16* __restrict__ Ah0, const __nv_bfloat16* __restrict__ Al0,
    const __nv_bfloat16* __restrict__ Ah1, const __nv_bfloat16* __restrict__ Al1,
    const float* __restrict__ bias0, const float* __restrict__ bias1,
    const __nv_bfloat16* __restrict__ Bh, const __nv_bfloat16* __restrict__ Bl,
    float* __restrict__ Y0, float* __restrict__ Y1, int Mhalf)
{
    extern __shared__ __align__(16) __nv_bfloat16 gsm[];
    __nv_bfloat16* sAh = gsm;                      // [2][128][APAD]
    __nv_bfloat16* sAl = sAh + 2 * A_ELT;
    __nv_bfloat16* sBh = sAl + 2 * A_ELT;          // [2][32][BPAD]
    __nv_bfloat16* sBl = sBh + 2 * B_ELT;

    const int tid  = threadIdx.x;
    const int lane = tid & 31;
    const int wid  = tid >> 5;
    const int wm   = wid >> 2;
    const int wn   = wid & 3;
    const int b    = blockIdx.z;
    const int l0   = blockIdx.y * 128;
    const int o0   = blockIdx.x * 128;

    const __nv_bfloat16 *Ah, *Al; const float* bi; float* Yb; int row0;
    if (o0 < Mhalf) { Ah = Ah0; Al = Al0; bi = bias0; Yb = Y0; row0 = o0; }
    else            { Ah = Ah1; Al = Al1; bi = bias1; Yb = Y1; row0 = o0 - Mhalf; }
    Ah += (size_t)row0 * NC;  Al += (size_t)row0 * NC;  bi += row0;
    const __nv_bfloat16* Bhb = Bh + (size_t)b * NC * NL + l0;
    const __nv_bfloat16* Blb = Bl + (size_t)b * NC * NL + l0;
    Yb += ((size_t)b * NO + row0) * NL + l0;

    const int ar = tid >> 1, ka  = (tid & 1) * 16;   // A: 2 thr/row, 16 bf16 each
    const int br = tid >> 3, blc = (tid & 7) * 16;   // B: 8 thr/row, 16 bf16 each
    const int aoff = ar * APAD + ka;
    const int boff = br * BPAD + blc;

    uint4 pah[2], pal[2], pbh[2], pbl[2];
    pah[0] = *(const uint4*)&Ah[(size_t)ar * NC + ka];
    pah[1] = *(const uint4*)&Ah[(size_t)ar * NC + ka + 8];
    pal[0] = *(const uint4*)&Al[(size_t)ar * NC + ka];
    pal[1] = *(const uint4*)&Al[(size_t)ar * NC + ka + 8];
    pbh[0] = *(const uint4*)&Bhb[(size_t)br * NL + blc];
    pbh[1] = *(const uint4*)&Bhb[(size_t)br * NL + blc + 8];
    pbl[0] = *(const uint4*)&Blb[(size_t)br * NL + blc];
    pbl[1] = *(const uint4*)&Blb[(size_t)br * NL + blc + 8];

    float acc[4][4][4];
#pragma unroll
    for (int i = 0; i < 4; i++)
#pragma unroll
        for (int j = 0; j < 4; j++)
#pragma unroll
            for (int r = 0; r < 4; r++) acc[i][j][r] = 0.f;

    const int a_row = wm * 64 + (lane & 15);
    const int a_col = (lane >> 4) * 8;
    const uint32_t aAh = cvta_smem(&sAh[a_row * APAD + a_col]);
    const uint32_t aAl = cvta_smem(&sAl[a_row * APAD + a_col]);
    const int b_row = (lane & 15);
    const int b_col = wn * 32 + (lane >> 4) * 8;
    const uint32_t aBh = cvta_smem(&sBh[b_row * BPAD + b_col]);
    const uint32_t aBl = cvta_smem(&sBl[b_row * BPAD + b_col]);

#pragma unroll 1
    for (int ch = 0; ch < 8; ch++) {
        const int q = ch & 1;
        const uint32_t qa = (uint32_t)(q * A_ELT * 2);
        const uint32_t qb = (uint32_t)(q * B_ELT * 2);
        *(uint4*)&sAh[q * A_ELT + aoff]      = pah[0];
        *(uint4*)&sAh[q * A_ELT + aoff + 8]  = pah[1];
        *(uint4*)&sAl[q * A_ELT + aoff]      = pal[0];
        *(uint4*)&sAl[q * A_ELT + aoff + 8]  = pal[1];
        *(uint4*)&sBh[q * B_ELT + boff]      = pbh[0];
        *(uint4*)&sBh[q * B_ELT + boff + 8]  = pbh[1];
        *(uint4*)&sBl[q * B_ELT + boff]      = pbl[0];
        *(uint4*)&sBl[q * B_ELT + boff + 8]  = pbl[1];
        __syncthreads();

        if (ch < 7) {
            const int k0 = (ch + 1) * 32;
            pah[0] = *(const uint4*)&Ah[(size_t)ar * NC + k0 + ka];
            pah[1] = *(const uint4*)&Ah[(size_t)ar * NC + k0 + ka + 8];
            pal[0] = *(const uint4*)&Al[(size_t)ar * NC + k0 + ka];
            pal[1] = *(const uint4*)&Al[(size_t)ar * NC + k0 + ka + 8];
            pbh[0] = *(const uint4*)&Bhb[(size_t)(k0 + br) * NL + blc];
            pbh[1] = *(const uint4*)&Bhb[(size_t)(k0 + br) * NL + blc + 8];
            pbl[0] = *(const uint4*)&Blb[(size_t)(k0 + br) * NL + blc];
            pbl[1] = *(const uint4*)&Blb[(size_t)(k0 + br) * NL + blc + 8];
        }

#pragma unroll
        for (int h = 0; h < 2; h++) {
            uint32_t bh[8], bl[8];
#pragma unroll
            for (int nt = 0; nt < 2; nt++) {
                const uint32_t off = (uint32_t)((h * 16) * BPAD + nt * 16) * 2;
                LDSM_X4_T(&bh[nt * 4], aBh + qb + off);
                LDSM_X4_T(&bl[nt * 4], aBl + qb + off);
            }
#pragma unroll
            for (int i = 0; i < 4; i++) {
                uint32_t ah[4], al[4];
                const uint32_t off = (uint32_t)((i * 16) * APAD + h * 16) * 2;
                LDSM_X4(ah, aAh + qa + off);
                LDSM_X4(al, aAl + qa + off);
#pragma unroll
                for (int j = 0; j < 4; j++) {
                    MMA_BF16(acc[i][j], ah, bh[j * 2], bh[j * 2 + 1]);
                    MMA_BF16(acc[i][j], ah, bl[j * 2], bl[j * 2 + 1]);
                    MMA_BF16(acc[i][j], al, bh[j * 2], bh[j * 2 + 1]);
                }
            }
        }
    }

    const int g   = lane >> 2;
    const int tig = lane & 3;
#pragma unroll
    for (int i = 0; i < 4; i++) {
        const int r0 = wm * 64 + i * 16 + g;
        const float bi0 = bi[r0];
        const float bi8 = bi[r0 + 8];
        float* y0 = Yb + (size_t)r0 * NL + wn * 32 + tig * 2;
        float* y8 = y0 + (size_t)8 * NL;
#pragma unroll
        for (int j = 0; j < 4; j++) {
            *(float2*)&y0[j * 8] = make_float2(acc[i][j][0] + bi0, acc[i][j][1] + bi0);
            *(float2*)&y8[j * 8] = make_float2(acc[i][j][2] + bi8, acc[i][j][3] + bi8);
        }
    }
}

// ---------------- BN stats (1024 thr, float4, shuffle reduce) ----------------
__device__ __forceinline__ void warp_red2(float& s, float& s2)
{
#pragma unroll
    for (int o = 16; o > 0; o >>= 1) {
        s  += __shfl_xor_sync(0xFFFFFFFFu, s,  o);
        s2 += __shfl_xor_sync(0xFFFFFFFFu, s2, o);
    }
}

__global__ __launch_bounds__(1024) void bn_stats12_kernel(
    const float* __restrict__ g1, const float* __restrict__ be1,
    const float* __restrict__ g2, const float* __restrict__ be2)
{
    const int ch = blockIdx.x & (NC - 1);
    const bool first = blockIdx.x < NC;
    const float* y = first ? g_y1 : g_y2;
    float s = 0.f, s2 = 0.f;
#pragma unroll
    for (int k = 0; k < 4; k++) {
        const int i = (threadIdx.x + k * 1024) * 4;
        const int b = i >> 12, l = i & (NL - 1);
        float4 v = *(const float4*)&y[((size_t)b * NC + ch) * NL + l];
        s  += (v.x + v.y) + (v.z + v.w);
        s2 += fmaf(v.x, v.x, v.y * v.y) + fmaf(v.z, v.z, v.w * v.w);
    }
    warp_red2(s, s2);
    __shared__ float rs[32], rq[32];
    const int lane = threadIdx.x & 31, wid = threadIdx.x >> 5;
    if (lane == 0) { rs[wid] = s; rq[wid] = s2; }
    __syncthreads();
    if (wid == 0) {
        s = rs[lane]; s2 = rq[lane];
        warp_red2(s, s2);
        if (lane == 0) {
            const float inv = 1.f / (float)(NB * NL);
            float mu  = s * inv;
            float var = s2 * inv - mu * mu;
            float gwv = first ? g1[ch] : g2[ch];
            float bwv = first ? be1[ch] : be2[ch];
            float r   = rsqrtf(var + NEPS) * gwv;
            if (first) { g_sc1[ch] = r; g_sh1[ch] = bwv - mu * r; }
            else       { g_sc2[ch] = r; g_sh2[ch] = bwv - mu * r; }
        }
    }
}

__global__ __launch_bounds__(1024) void bn_statsF_relu_kernel(
    float* __restrict__ y,
    const float* __restrict__ gw, const float* __restrict__ bw)
{
    const int ch = blockIdx.x;
    float4 vv[4];
    size_t addr[4];
    float s = 0.f, s2 = 0.f;
#pragma unroll
    for (int k = 0; k < 4; k++) {
        const int i = (threadIdx.x + k * 1024) * 4;
        const int b = i >> 12, l = i & (NL - 1);
        addr[k] = ((size_t)b * NO + ch) * NL + l;
        float4 v = *(const float4*)&y[addr[k]];
        vv[k] = v;
        s  += (v.x + v.y) + (v.z + v.w);
        s2 += fmaf(v.x, v.x, v.y * v.y) + fmaf(v.z, v.z, v.w * v.w);
    }
    warp_red2(s, s2);
    __shared__ float rs[32], rq[32];
    __shared__ float bcast[2];
    const int lane = threadIdx.x & 31, wid = threadIdx.x >> 5;
    if (lane == 0) { rs[wid] = s; rq[wid] = s2; }
    __syncthreads();
    if (wid == 0) {
        s = rs[lane]; s2 = rq[lane];
        warp_red2(s, s2);
        if (lane == 0) {
            const float inv = 1.f / (float)(NB * NL);
            float mu  = s * inv;
            float var = s2 * inv - mu * mu;
            float r   = rsqrtf(var + NEPS) * gw[ch];
            bcast[0] = r;
            bcast[1] = bw[ch] - mu * r;
        }
    }
    __syncthreads();
    const float sc = bcast[0], sh = bcast[1];
#pragma unroll
    for (int k = 0; k < 4; k++) {
        float4 v = vv[k];
        v.x = fmaxf(fmaf(v.x, sc, sh), 0.f);
        v.y = fmaxf(fmaf(v.y, sc, sh), 0.f);
        v.z = fmaxf(fmaf(v.z, sc, sh), 0.f);
        v.w = fmaxf(fmaf(v.w, sc, sh), 0.f);
        *(float4*)&y[addr[k]] = v;
    }
}

// ---------------- scrambled-unfold attention: weight-plane formulation ---------------
// Phase 1 writes softmax weights w[n] into smem; fast path for groups that cross
// neither an image row nor a p-plane boundary ((l0&63)<=55): 9 contiguous cells,
// immediate-offset LDS, zero per-tap addressing ALU.
__global__ __launch_bounds__(ATT_THREADS, 1) void att_kernel(const float* __restrict__ x)
{
    extern __shared__ float sm[];
    float* t12 = sm + ATT_F_T12;   // 66x66 interleaved (tri1, tri2) float2
    float* xs  = sm + ATT_F_XS;    // 66x66 padded x plane
    float* w   = sm + ATT_F_W;     // 36864 softmax weights

    const int bc = blockIdx.x;
    const int c  = bc & (NC - 1);
    const size_t base = (size_t)bc * NL;
    const float sc1 = g_sc1[c], sh1 = g_sh1[c];
    const float sc2 = g_sc2[c], sh2 = g_sh2[c];

    for (int i = threadIdx.x; i < 4356; i += ATT_THREADS) xs[i] = 0.f;
    for (int i = threadIdx.x; i < 8712; i += ATT_THREADS) t12[i] = 0.f;
    __syncthreads();

    {
        const int l4 = threadIdx.x * 4;      // exactly covers 0..4092
        float4 xv = *(const float4*)&x[base + l4];
        float4 a  = *(const float4*)&g_y1[base + l4];
        float4 q  = *(const float4*)&g_y2[base + l4];
        const int pidx = (l4 >> 6) * 66 + (l4 & 63) + 67;
        xs[pidx+0] = xv.x; xs[pidx+1] = xv.y; xs[pidx+2] = xv.z; xs[pidx+3] = xv.w;
        float t1v[4] = {
            fmaxf(fmaf(a.x, sc1, sh1), 0.f), fmaxf(fmaf(a.y, sc1, sh1), 0.f),
            fmaxf(fmaf(a.z, sc1, sh1), 0.f), fmaxf(fmaf(a.w, sc1, sh1), 0.f) };
        float t2v[4] = {
            fmaxf(fmaf(q.x, sc2, sh2), 0.f), fmaxf(fmaf(q.y, sc2, sh2), 0.f),
            fmaxf(fmaf(q.z, sc2, sh2), 0.f), fmaxf(fmaf(q.w, sc2, sh2), 0.f) };
#pragma unroll
        for (int j = 0; j < 4; j++)
            *(float2*)&t12[2 * (pidx + j)] = make_float2(t1v[j], t2v[j]);
    }
    __syncthreads();

    // phase 1: per group (9 consecutive n), emit the 9 softmax weights
#pragma unroll
    for (int k = 0; k < 4; k++) {
        const int g  = threadIdx.x + k * ATT_THREADS;
        const int n0 = 9 * g;
        const int p0 = n0 >> 12;
        const int l0 = n0 & (NL - 1);
        float ku[9], qu[9];
        if ((l0 & 63) <= 55) {
            // fast path: no row crossing, no plane crossing -> contiguous cells
            const int di0 = (p0 * 171) >> 9, dj0 = p0 - 3 * di0;
            const int idx0 = (l0 >> 6) * 66 + (l0 & 63) + di0 * 66 + dj0;
            const float2* tp = (const float2*)&t12[2 * idx0];
#pragma unroll
            for (int r = 0; r < 9; r++) {
                const float2 kq = tp[r];      // immediate-offset LDS
                ku[r] = kq.x; qu[r] = kq.y;
            }
        } else {
            const int di0 = (p0 * 171) >> 9, dj0 = p0 - 3 * di0;
            const int p1  = p0 + 1;
            const int di1 = (p1 * 171) >> 9, dj1 = p1 - 3 * di1;
            const int C0 = di0 * 66 + dj0;
            const int C1 = di1 * 66 + dj1 - 4224;
#pragma unroll
            for (int r = 0; r < 9; r++) {
                const int l = l0 + r;
                const int C = (l >> 12) ? C1 : C0;
                const int idx = (l >> 6) * 66 + (l & 63) + C;
                const float2 kq = *(const float2*)&t12[2 * idx];
                ku[r] = kq.x; qu[r] = kq.y;
            }
        }
        const float quC = qu[4] * LOG2E;
        const float kuC = ku[4] * LOG2E;
        float lg[9];
        float m = -1e30f;
#pragma unroll
        for (int r = 0; r < 9; r++) {
            lg[r] = fmaf(ku[r], quC, kuC * qu[r]);
            m = fmaxf(m, lg[r]);
        }
        float e[9];
        float s = 0.f;
#pragma unroll
        for (int r = 0; r < 9; r++) {
            EX2_APPROX(e[r], lg[r] - m);
            s += e[r];
        }
        const float inv = __fdividef(1.f, s);
#pragma unroll
        for (int r = 0; r < 9; r++)
            w[n0 + r] = e[r] * inv;
    }
    __syncthreads();

    // phase 2: weighted gather; w loads are float4-contiguous in l
    {
        const int l4  = threadIdx.x * 4;
        const int row = l4 >> 6, col = l4 & 63;
        float acc[4] = {0.f, 0.f, 0.f, 0.f};
#pragma unroll
        for (int tr = 0; tr < 3; tr++) {
            const int pb = (row + tr) * 66 + col;
            float xv[6];
#pragma unroll
            for (int k = 0; k < 6; k++) xv[k] = xs[pb + k];
#pragma unroll
            for (int dj = 0; dj < 3; dj++) {
                const int p = tr * 3 + dj;
                const float4 wv = *(const float4*)&w[(p << 12) + l4];
                acc[0] = fmaf(wv.x, xv[dj + 0], acc[0]);
                acc[1] = fmaf(wv.y, xv[dj + 1], acc[1]);
                acc[2] = fmaf(wv.z, xv[dj + 2], acc[2]);
                acc[3] = fmaf(wv.w, xv[dj + 3], acc[3]);
            }
        }
        uint32_t oh, ol, oh2, ol2;
        {
            __nv_bfloat16 h0 = __float2bfloat16(acc[0]);
            __nv_bfloat16 h1 = __float2bfloat16(acc[1]);
            __nv_bfloat16 l0b = __float2bfloat16(acc[0] - __bfloat162float(h0));
            __nv_bfloat16 l1b = __float2bfloat16(acc[1] - __bfloat162float(h1));
            __nv_bfloat162 ph = __halves2bfloat162(h0, h1);
            __nv_bfloat162 pl = __halves2bfloat162(l0b, l1b);
            oh = *(uint32_t*)&ph; ol = *(uint32_t*)&pl;
        }
        {
            __nv_bfloat16 h2 = __float2bfloat16(acc[2]);
            __nv_bfloat16 h3 = __float2bfloat16(acc[3]);
            __nv_bfloat16 l2b = __float2bfloat16(acc[2] - __bfloat162float(h2));
            __nv_bfloat16 l3b = __float2bfloat16(acc[3] - __bfloat162float(h3));
            __nv_bfloat162 ph = __halves2bfloat162(h2, h3);
            __nv_bfloat162 pl = __halves2bfloat162(l2b, l3b);
            oh2 = *(uint32_t*)&ph; ol2 = *(uint32_t*)&pl;
        }
        *(uint2*)&g_ph[base + l4] = make_uint2(oh, oh2);
        *(uint2*)&g_pl[base + l4] = make_uint2(ol, ol2);
    }
}

// ---------------- launch ----------------
extern "C" void kernel_launch(void* const* d_in, const int* in_sizes, int n_in,
                              void* d_out, int out_size)
{
    (void)in_sizes; (void)n_in; (void)out_size;
    const float* x   = (const float*)d_in[0];
    const float* w1  = (const float*)d_in[1];
    const float* b1  = (const float*)d_in[2];
    const float* g1  = (const float*)d_in[3];
    const float* be1 = (const float*)d_in[4];
    const float* w2  = (const float*)d_in[5];
    const float* b2  = (const float*)d_in[6];
    const float* g2  = (const float*)d_in[7];
    const float* be2 = (const float*)d_in[8];
    const float* wf  = (const float*)d_in[9];
    const float* bf  = (const float*)d_in[10];
    const float* gf  = (const float*)d_in[11];
    const float* bef = (const float*)d_in[12];
    float* out = (float*)d_out;

    cudaFuncSetAttribute(att_kernel, cudaFuncAttributeMaxDynamicSharedMemorySize,
                         ATT_SMEM_BYTES);
    cudaFuncSetAttribute(mma_gemm_kernel, cudaFuncAttributeMaxDynamicSharedMemorySize,
                         GEMM_SMEM_BYTES);

    float* y1p;  cudaGetSymbolAddress((void**)&y1p,  g_y1);
    float* y2p;  cudaGetSymbolAddress((void**)&y2p,  g_y2);
    __nv_bfloat16 *xh, *xl, *ph, *pl, *wh, *wl, *wfh, *wfl;
    cudaGetSymbolAddress((void**)&xh,  g_xh);
    cudaGetSymbolAddress((void**)&xl,  g_xl);
    cudaGetSymbolAddress((void**)&ph,  g_ph);
    cudaGetSymbolAddress((void**)&pl,  g_pl);
    cudaGetSymbolAddress((void**)&wh,  g_wh);
    cudaGetSymbolAddress((void**)&wl,  g_wl);
    cudaGetSymbolAddress((void**)&wfh, g_wfh);
    cudaGetSymbolAddress((void**)&wfl, g_wfl);

    conv_all_kernel<<<CONV_X_BLOCKS + CONV_W_BLOCKS, 256>>>(x, w1, w2, wf);

    // dual GEMM: stacked M=512 (rows 0-255 -> w1/y1, 256-511 -> w2/y2)
    dim3 gd(4, NL / 128, NB);
    mma_gemm_kernel<<<gd, 256, GEMM_SMEM_BYTES>>>(wh, wl, wh + NC * NC, wl + NC * NC,
                                                  b1, b2, xh, xl, y1p, y2p, 256);
    bn_stats12_kernel<<<2 * NC, 1024>>>(g1, be1, g2, be2);
    att_kernel<<<NB * NC, ATT_THREADS, ATT_SMEM_BYTES>>>(x);
    // final GEMM: M=256 single matrix
    dim3 gf2(2, NL / 128, NB);
    mma_gemm_kernel<<<gf2, 256, GEMM_SMEM_BYTES>>>(wfh, wfl, wfh, wfl, bf, bf,
                                                   ph, pl, out, out, 512);
    bn_statsF_relu_kernel<<<NO, 1024>>>(out, gf, bef);
}

// round 10
// speedup vs baseline: 1.0501x; 1.0501x over previous
#include <cuda_runtime.h>
#include <cuda_bf16.h>
#include <cuda_fp16.h>
#include <stdint.h>

#define NB 4
#define NC 256
#define NO 256
#define NL 4096          // H*W
#define NEPS 1e-5f
#define LOG2E 1.4426950408889634f

#define ATT_THREADS 1024
// smem floats: t12 8712 (66x66 float2) | xs 4356 | w 36864 = 49932 floats (199728 B)
#define ATT_F_T12  0
#define ATT_F_XS   8712
#define ATT_F_W    (8712 + 4356)
#define ATT_SMEM_BYTES ((8712 + 4356 + 36864) * 4)

#define EX2_APPROX(d, a) \
    asm("ex2.approx.ftz.f32 %0, %1;" : "=f"(d) : "f"(a))

// ---- tensor-core helpers (canonical m16n8k16 bf16 fragments) ----
#define LDSM_X4(r, a) \
    asm volatile("ldmatrix.sync.aligned.m8n8.x4.shared.b16 {%0,%1,%2,%3}, [%4];" \
        : "=r"((r)[0]), "=r"((r)[1]), "=r"((r)[2]), "=r"((r)[3]) : "r"(a))
#define LDSM_X4_T(r, a) \
    asm volatile("ldmatrix.sync.aligned.m8n8.x4.trans.shared.b16 {%0,%1,%2,%3}, [%4];" \
        : "=r"((r)[0]), "=r"((r)[1]), "=r"((r)[2]), "=r"((r)[3]) : "r"(a))
#define MMA_BF16(c, a, b0_, b1_) \
    asm volatile("mma.sync.aligned.m16n8k16.row.col.f32.bf16.bf16.f32 " \
        "{%0,%1,%2,%3}, {%4,%5,%6,%7}, {%8,%9}, {%0,%1,%2,%3};" \
        : "+f"((c)[0]), "+f"((c)[1]), "+f"((c)[2]), "+f"((c)[3]) \
        : "r"((a)[0]), "r"((a)[1]), "r"((a)[2]), "r"((a)[3]), "r"(b0_), "r"(b1_))

__device__ __forceinline__ uint32_t cvta_smem(const void* p) {
    return (uint32_t)__cvta_generic_to_shared(p);
}

// ---------------- scratch (static device globals; no runtime allocs) ----------------
static __device__ __half g_y1h[NB*NC*NL];
static __device__ __half g_y2h[NB*NC*NL];
static __device__ __nv_bfloat16 g_xh[NB*NC*NL],  g_xl[NB*NC*NL];
static __device__ __nv_bfloat16 g_ph[NB*NC*NL],  g_pl[NB*NC*NL];
static __device__ __nv_bfloat16 g_wh[2*NC*NC],   g_wl[2*NC*NC];     // w1 | w2 stacked
static __device__ __nv_bfloat16 g_wfh[NO*NC],    g_wfl[NO*NC];
static __device__ float g_sc1[NC], g_sh1[NC];
static __device__ float g_sc2[NC], g_sh2[NC];

// ---------------- fp32 -> bf16 hi/lo conversion (x and all weights, one launch) -----
__device__ __forceinline__ void split2(const float a, const float b,
                                       __nv_bfloat162* dh, __nv_bfloat162* dl)
{
    __nv_bfloat16 ha = __float2bfloat16(a), hb = __float2bfloat16(b);
    __nv_bfloat16 la = __float2bfloat16(a - __bfloat162float(ha));
    __nv_bfloat16 lb = __float2bfloat16(b - __bfloat162float(hb));
    *dh = __halves2bfloat162(ha, hb);
    *dl = __halves2bfloat162(la, lb);
}

#define CONV_X_BLOCKS ((NB*NC*NL) / (256 * 4))      // 16384
#define CONV_W_BLOCKS ((3*NC*NC) / (256 * 4))       // 192

__global__ __launch_bounds__(256) void conv_all_kernel(
    const float* __restrict__ x,
    const float* __restrict__ w1, const float* __restrict__ w2,
    const float* __restrict__ wf)
{
    if (blockIdx.x < CONV_X_BLOCKS) {
        const int i = (blockIdx.x * 256 + threadIdx.x) * 4;
        float4 v = *(const float4*)&x[i];
        split2(v.x, v.y, (__nv_bfloat162*)&g_xh[i],     (__nv_bfloat162*)&g_xl[i]);
        split2(v.z, v.w, (__nv_bfloat162*)&g_xh[i + 2], (__nv_bfloat162*)&g_xl[i + 2]);
    } else {
        const int i = ((blockIdx.x - CONV_X_BLOCKS) * 256 + threadIdx.x) * 4;
        float4 v;
        __nv_bfloat162 *dh, *dl;
        if (i < 65536)       { v = *(const float4*)&w1[i];          dh = (__nv_bfloat162*)&g_wh[i];  dl = (__nv_bfloat162*)&g_wl[i]; }
        else if (i < 131072) { v = *(const float4*)&w2[i - 65536];  dh = (__nv_bfloat162*)&g_wh[i];  dl = (__nv_bfloat162*)&g_wl[i]; }
        else                 { v = *(const float4*)&wf[i - 131072]; dh = (__nv_bfloat162*)&g_wfh[i - 131072]; dl = (__nv_bfloat162*)&g_wfl[i - 131072]; }
        split2(v.x, v.y, dh,     dl);
        split2(v.z, v.w, dh + 1, dl + 1);
    }
}

// ---------------- bf16x3 tensor-core GEMM (pre-split, smem double-buffered) ---------
// OutT = __half (y1/y2) or float (final out)
#define APAD 40
#define BPAD 136
#define A_ELT (128 * APAD)     // 5120 bf16 per A buffer
#define B_ELT (32 * BPAD)      // 4352 bf16 per B buffer
#define GEMM_SMEM_BYTES ((2 * A_ELT * 2 + 2 * B_ELT * 2) * 2)   // 75776 B

template <typename OutT>
__global__ __launch_bounds__(256) void mma_gemm_kernel(
    const __nv_bfloat16* __restrict__ Ah0, const __nv_bfloat16* __restrict__ Al0,
    const __nv_bfloat16* __restrict__ Ah1, const __nv_bfloat16* __restrict__ Al1,
    const float* __restrict__ bias0, const float* __restrict__ bias1,
    const __nv_bfloat16* __restrict__ Bh, const __nv_bfloat16* __restrict__ Bl,
    OutT* __restrict__ Y0, OutT* __restrict__ Y1, int Mhalf)
{
    extern __shared__ __align__(16) __nv_bfloat16 gsm[];
    __nv_bfloat16* sAh = gsm;                      // [2][128][APAD]
    __nv_bfloat16* sAl = sAh + 2 * A_ELT;
    __nv_bfloat16* sBh = sAl + 2 * A_ELT;          // [2][32][BPAD]
    __nv_bfloat16* sBl = sBh + 2 * B_ELT;

    const int tid  = threadIdx.x;
    const int lane = tid & 31;
    const int wid  = tid >> 5;
    const int wm   = wid >> 2;
    const int wn   = wid & 3;
    const int b    = blockIdx.z;
    const int l0   = blockIdx.y * 128;
    const int o0   = blockIdx.x * 128;

    const __nv_bfloat16 *Ah, *Al; const float* bi; OutT* Yb; int row0;
    if (o0 < Mhalf) { Ah = Ah0; Al = Al0; bi = bias0; Yb = Y0; row0 = o0; }
    else            { Ah = Ah1; Al = Al1; bi = bias1; Yb = Y1; row0 = o0 - Mhalf; }
    Ah += (size_t)row0 * NC;  Al += (size_t)row0 * NC;  bi += row0;
    const __nv_bfloat16* Bhb = Bh + (size_t)b * NC * NL + l0;
    const __nv_bfloat16* Blb = Bl + (size_t)b * NC * NL + l0;
    Yb += ((size_t)b * NO + row0) * NL + l0;

    const int ar = tid >> 1, ka  = (tid & 1) * 16;   // A: 2 thr/row, 16 bf16 each
    const int br = tid >> 3, blc = (tid & 7) * 16;   // B: 8 thr/row, 16 bf16 each
    const int aoff = ar * APAD + ka;
    const int boff = br * BPAD + blc;

    uint4 pah[2], pal[2], pbh[2], pbl[2];
    pah[0] = *(const uint4*)&Ah[(size_t)ar * NC + ka];
    pah[1] = *(const uint4*)&Ah[(size_t)ar * NC + ka + 8];
    pal[0] = *(const uint4*)&Al[(size_t)ar * NC + ka];
    pal[1] = *(const uint4*)&Al[(size_t)ar * NC + ka + 8];
    pbh[0] = *(const uint4*)&Bhb[(size_t)br * NL + blc];
    pbh[1] = *(const uint4*)&Bhb[(size_t)br * NL + blc + 8];
    pbl[0] = *(const uint4*)&Blb[(size_t)br * NL + blc];
    pbl[1] = *(const uint4*)&Blb[(size_t)br * NL + blc + 8];

    float acc[4][4][4];
#pragma unroll
    for (int i = 0; i < 4; i++)
#pragma unroll
        for (int j = 0; j < 4; j++)
#pragma unroll
            for (int r = 0; r < 4; r++) acc[i][j][r] = 0.f;

    const int a_row = wm * 64 + (lane & 15);
    const int a_col = (lane >> 4) * 8;
    const uint32_t aAh = cvta_smem(&sAh[a_row * APAD + a_col]);
    const uint32_t aAl = cvta_smem(&sAl[a_row * APAD + a_col]);
    const int b_row = (lane & 15);
    const int b_col = wn * 32 + (lane >> 4) * 8;
    const uint32_t aBh = cvta_smem(&sBh[b_row * BPAD + b_col]);
    const uint32_t aBl = cvta_smem(&sBl[b_row * BPAD + b_col]);

#pragma unroll 1
    for (int ch = 0; ch < 8; ch++) {
        const int q = ch & 1;
        const uint32_t qa = (uint32_t)(q * A_ELT * 2);
        const uint32_t qb = (uint32_t)(q * B_ELT * 2);
        *(uint4*)&sAh[q * A_ELT + aoff]      = pah[0];
        *(uint4*)&sAh[q * A_ELT + aoff + 8]  = pah[1];
        *(uint4*)&sAl[q * A_ELT + aoff]      = pal[0];
        *(uint4*)&sAl[q * A_ELT + aoff + 8]  = pal[1];
        *(uint4*)&sBh[q * B_ELT + boff]      = pbh[0];
        *(uint4*)&sBh[q * B_ELT + boff + 8]  = pbh[1];
        *(uint4*)&sBl[q * B_ELT + boff]      = pbl[0];
        *(uint4*)&sBl[q * B_ELT + boff + 8]  = pbl[1];
        __syncthreads();

        if (ch < 7) {
            const int k0 = (ch + 1) * 32;
            pah[0] = *(const uint4*)&Ah[(size_t)ar * NC + k0 + ka];
            pah[1] = *(const uint4*)&Ah[(size_t)ar * NC + k0 + ka + 8];
            pal[0] = *(const uint4*)&Al[(size_t)ar * NC + k0 + ka];
            pal[1] = *(const uint4*)&Al[(size_t)ar * NC + k0 + ka + 8];
            pbh[0] = *(const uint4*)&Bhb[(size_t)(k0 + br) * NL + blc];
            pbh[1] = *(const uint4*)&Bhb[(size_t)(k0 + br) * NL + blc + 8];
            pbl[0] = *(const uint4*)&Blb[(size_t)(k0 + br) * NL + blc];
            pbl[1] = *(const uint4*)&Blb[(size_t)(k0 + br) * NL + blc + 8];
        }

#pragma unroll
        for (int h = 0; h < 2; h++) {
            uint32_t bh[8], bl[8];
#pragma unroll
            for (int nt = 0; nt < 2; nt++) {
                const uint32_t off = (uint32_t)((h * 16) * BPAD + nt * 16) * 2;
                LDSM_X4_T(&bh[nt * 4], aBh + qb + off);
                LDSM_X4_T(&bl[nt * 4], aBl + qb + off);
            }
#pragma unroll
            for (int i = 0; i < 4; i++) {
                uint32_t ah[4], al[4];
                const uint32_t off = (uint32_t)((i * 16) * APAD + h * 16) * 2;
                LDSM_X4(ah, aAh + qa + off);
                LDSM_X4(al, aAl + qa + off);
#pragma unroll
                for (int j = 0; j < 4; j++) {
                    MMA_BF16(acc[i][j], ah, bh[j * 2], bh[j * 2 + 1]);
                    MMA_BF16(acc[i][j], ah, bl[j * 2], bl[j * 2 + 1]);
                    MMA_BF16(acc[i][j], al, bh[j * 2], bh[j * 2 + 1]);
                }
            }
        }
    }

    const int g   = lane >> 2;
    const int tig = lane & 3;
#pragma unroll
    for (int i = 0; i < 4; i++) {
        const int r0 = wm * 64 + i * 16 + g;
        const float bi0 = bi[r0];
        const float bi8 = bi[r0 + 8];
        OutT* y0 = Yb + (size_t)r0 * NL + wn * 32 + tig * 2;
        OutT* y8 = y0 + (size_t)8 * NL;
#pragma unroll
        for (int j = 0; j < 4; j++) {
            if (sizeof(OutT) == 2) {
                *(__half2*)&y0[j * 8] = __floats2half2_rn(acc[i][j][0] + bi0, acc[i][j][1] + bi0);
                *(__half2*)&y8[j * 8] = __floats2half2_rn(acc[i][j][2] + bi8, acc[i][j][3] + bi8);
            } else {
                *(float2*)&y0[j * 8] = make_float2(acc[i][j][0] + bi0, acc[i][j][1] + bi0);
                *(float2*)&y8[j * 8] = make_float2(acc[i][j][2] + bi8, acc[i][j][3] + bi8);
            }
        }
    }
}

// ---------------- BN stats (1024 thr, shuffle reduce) ----------------
__device__ __forceinline__ void warp_red2(float& s, float& s2)
{
#pragma unroll
    for (int o = 16; o > 0; o >>= 1) {
        s  += __shfl_xor_sync(0xFFFFFFFFu, s,  o);
        s2 += __shfl_xor_sync(0xFFFFFFFFu, s2, o);
    }
}

__global__ __launch_bounds__(1024) void bn_stats12_kernel(
    const float* __restrict__ g1, const float* __restrict__ be1,
    const float* __restrict__ g2, const float* __restrict__ be2)
{
    const int ch = blockIdx.x & (NC - 1);
    const bool first = blockIdx.x < NC;
    const __half* y = first ? g_y1h : g_y2h;
    float s = 0.f, s2 = 0.f;
#pragma unroll
    for (int k = 0; k < 2; k++) {
        const int i = (threadIdx.x + k * 1024) * 8;      // 8 halves per load
        const int b = i >> 12, l = i & (NL - 1);
        const uint4 u = *(const uint4*)&y[((size_t)b * NC + ch) * NL + l];
        const __half2* hp = (const __half2*)&u;
#pragma unroll
        for (int t = 0; t < 4; t++) {
            float2 f = __half22float2(hp[t]);
            s  += f.x + f.y;
            s2 += fmaf(f.x, f.x, f.y * f.y);
        }
    }
    warp_red2(s, s2);
    __shared__ float rs[32], rq[32];
    const int lane = threadIdx.x & 31, wid = threadIdx.x >> 5;
    if (lane == 0) { rs[wid] = s; rq[wid] = s2; }
    __syncthreads();
    if (wid == 0) {
        s = rs[lane]; s2 = rq[lane];
        warp_red2(s, s2);
        if (lane == 0) {
            const float inv = 1.f / (float)(NB * NL);
            float mu  = s * inv;
            float var = s2 * inv - mu * mu;
            float gwv = first ? g1[ch] : g2[ch];
            float bwv = first ? be1[ch] : be2[ch];
            float r   = rsqrtf(var + NEPS) * gwv;
            if (first) { g_sc1[ch] = r; g_sh1[ch] = bwv - mu * r; }
            else       { g_sc2[ch] = r; g_sh2[ch] = bwv - mu * r; }
        }
    }
}

__global__ __launch_bounds__(1024) void bn_statsF_relu_kernel(
    float* __restrict__ y,
    const float* __restrict__ gw, const float* __restrict__ bw)
{
    const int ch = blockIdx.x;
    float4 vv[4];
    size_t addr[4];
    float s = 0.f, s2 = 0.f;
#pragma unroll
    for (int k = 0; k < 4; k++) {
        const int i = (threadIdx.x + k * 1024) * 4;
        const int b = i >> 12, l = i & (NL - 1);
        addr[k] = ((size_t)b * NO + ch) * NL + l;
        float4 v = *(const float4*)&y[addr[k]];
        vv[k] = v;
        s  += (v.x + v.y) + (v.z + v.w);
        s2 += fmaf(v.x, v.x, v.y * v.y) + fmaf(v.z, v.z, v.w * v.w);
    }
    warp_red2(s, s2);
    __shared__ float rs[32], rq[32];
    __shared__ float bcast[2];
    const int lane = threadIdx.x & 31, wid = threadIdx.x >> 5;
    if (lane == 0) { rs[wid] = s; rq[wid] = s2; }
    __syncthreads();
    if (wid == 0) {
        s = rs[lane]; s2 = rq[lane];
        warp_red2(s, s2);
        if (lane == 0) {
            const float inv = 1.f / (float)(NB * NL);
            float mu  = s * inv;
            float var = s2 * inv - mu * mu;
            float r   = rsqrtf(var + NEPS) * gw[ch];
            bcast[0] = r;
            bcast[1] = bw[ch] - mu * r;
        }
    }
    __syncthreads();
    const float sc = bcast[0], sh = bcast[1];
#pragma unroll
    for (int k = 0; k < 4; k++) {
        float4 v = vv[k];
        v.x = fmaxf(fmaf(v.x, sc, sh), 0.f);
        v.y = fmaxf(fmaf(v.y, sc, sh), 0.f);
        v.z = fmaxf(fmaf(v.z, sc, sh), 0.f);
        v.w = fmaxf(fmaf(v.w, sc, sh), 0.f);
        *(float4*)&y[addr[k]] = v;
    }
}

// ---------------- scrambled-unfold attention: weight-plane formulation ---------------
// Phase 1 writes softmax weights into smem (no max-subtraction: ReLU => logits >= 0,
// bounded well below fp32 overflow; ratios identical). Phase 2 is a weighted gather.
__global__ __launch_bounds__(ATT_THREADS, 1) void att_kernel(const float* __restrict__ x)
{
    extern __shared__ float sm[];
    float* t12 = sm + ATT_F_T12;   // 66x66 interleaved (tri1, tri2) float2
    float* xs  = sm + ATT_F_XS;    // 66x66 padded x plane
    float* w   = sm + ATT_F_W;     // 36864 softmax weights

    const int bc = blockIdx.x;
    const int c  = bc & (NC - 1);
    const size_t base = (size_t)bc * NL;
    const float sc1 = g_sc1[c], sh1 = g_sh1[c];
    const float sc2 = g_sc2[c], sh2 = g_sh2[c];

    for (int i = threadIdx.x; i < 4356; i += ATT_THREADS) xs[i] = 0.f;
    for (int i = threadIdx.x; i < 8712; i += ATT_THREADS) t12[i] = 0.f;
    __syncthreads();

    {
        const int l4 = threadIdx.x * 4;      // exactly covers 0..4092
        float4 xv = *(const float4*)&x[base + l4];
        const __half2* ap = (const __half2*)(g_y1h + base + l4);
        const __half2* qp = (const __half2*)(g_y2h + base + l4);
        float2 a01 = __half22float2(ap[0]), a23 = __half22float2(ap[1]);
        float2 q01 = __half22float2(qp[0]), q23 = __half22float2(qp[1]);
        const int pidx = (l4 >> 6) * 66 + (l4 & 63) + 67;
        xs[pidx+0] = xv.x; xs[pidx+1] = xv.y; xs[pidx+2] = xv.z; xs[pidx+3] = xv.w;
        float t1v[4] = {
            fmaxf(fmaf(a01.x, sc1, sh1), 0.f), fmaxf(fmaf(a01.y, sc1, sh1), 0.f),
            fmaxf(fmaf(a23.x, sc1, sh1), 0.f), fmaxf(fmaf(a23.y, sc1, sh1), 0.f) };
        float t2v[4] = {
            fmaxf(fmaf(q01.x, sc2, sh2), 0.f), fmaxf(fmaf(q01.y, sc2, sh2), 0.f),
            fmaxf(fmaf(q23.x, sc2, sh2), 0.f), fmaxf(fmaf(q23.y, sc2, sh2), 0.f) };
#pragma unroll
        for (int j = 0; j < 4; j++)
            *(float2*)&t12[2 * (pidx + j)] = make_float2(t1v[j], t2v[j]);
    }
    __syncthreads();

    // phase 1: per group (9 consecutive n), emit the 9 softmax weights
    for (int g = threadIdx.x; g < NL; g += ATT_THREADS) {
        const int n0 = 9 * g;
        const int p0 = n0 >> 12;
        const int l0 = n0 & (NL - 1);
        const int di0 = (p0 * 171) >> 9, dj0 = p0 - 3 * di0;
        const int p1 = p0 + 1;
        const int di1 = (p1 * 171) >> 9, dj1 = p1 - 3 * di1;
        const int C0 = di0 * 66 + dj0;
        const int C1 = di1 * 66 + dj1 - 4224;
        float ku[9], qu[9];
#pragma unroll
        for (int r = 0; r < 9; r++) {
            const int l = l0 + r;
            const int C = (l >> 12) ? C1 : C0;
            const int idx = (l >> 6) * 66 + (l & 63) + C;
            const float2 kq = *(const float2*)&t12[2 * idx];
            ku[r] = kq.x; qu[r] = kq.y;
        }
        const float quC = qu[4] * LOG2E;
        const float kuC = ku[4] * LOG2E;
        float e[9];
        float s = 0.f;
#pragma unroll
        for (int r = 0; r < 9; r++) {
            const float lg = fmaf(ku[r], quC, kuC * qu[r]);
            EX2_APPROX(e[r], lg);
            s += e[r];
        }
        const float inv = __fdividef(1.f, s);
#pragma unroll
        for (int r = 0; r < 9; r++)
            w[n0 + r] = e[r] * inv;
    }
    __syncthreads();

    // phase 2: weighted gather; w loads are float4-contiguous in l
    {
        const int l4  = threadIdx.x * 4;
        const int row = l4 >> 6, col = l4 & 63;
        float acc[4] = {0.f, 0.f, 0.f, 0.f};
#pragma unroll
        for (int tr = 0; tr < 3; tr++) {
            const int pb = (row + tr) * 66 + col;
            float xv[6];
#pragma unroll
            for (int k = 0; k < 6; k++) xv[k] = xs[pb + k];
#pragma unroll
            for (int dj = 0; dj < 3; dj++) {
                const int p = tr * 3 + dj;
                const float4 wv = *(const float4*)&w[(p << 12) + l4];
                acc[0] = fmaf(wv.x, xv[dj + 0], acc[0]);
                acc[1] = fmaf(wv.y, xv[dj + 1], acc[1]);
                acc[2] = fmaf(wv.z, xv[dj + 2], acc[2]);
                acc[3] = fmaf(wv.w, xv[dj + 3], acc[3]);
            }
        }
        uint32_t oh, ol, oh2, ol2;
        {
            __nv_bfloat16 h0 = __float2bfloat16(acc[0]);
            __nv_bfloat16 h1 = __float2bfloat16(acc[1]);
            __nv_bfloat16 l0b = __float2bfloat16(acc[0] - __bfloat162float(h0));
            __nv_bfloat16 l1b = __float2bfloat16(acc[1] - __bfloat162float(h1));
            __nv_bfloat162 ph = __halves2bfloat162(h0, h1);
            __nv_bfloat162 pl = __halves2bfloat162(l0b, l1b);
            oh = *(uint32_t*)&ph; ol = *(uint32_t*)&pl;
        }
        {
            __nv_bfloat16 h2 = __float2bfloat16(acc[2]);
            __nv_bfloat16 h3 = __float2bfloat16(acc[3]);
            __nv_bfloat16 l2b = __float2bfloat16(acc[2] - __bfloat162float(h2));
            __nv_bfloat16 l3b = __float2bfloat16(acc[3] - __bfloat162float(h3));
            __nv_bfloat162 ph = __halves2bfloat162(h2, h3);
            __nv_bfloat162 pl = __halves2bfloat162(l2b, l3b);
            oh2 = *(uint32_t*)&ph; ol2 = *(uint32_t*)&pl;
        }
        *(uint2*)&g_ph[base + l4] = make_uint2(oh, oh2);
        *(uint2*)&g_pl[base + l4] = make_uint2(ol, ol2);
    }
}

// ---------------- launch ----------------
extern "C" void kernel_launch(void* const* d_in, const int* in_sizes, int n_in,
                              void* d_out, int out_size)
{
    (void)in_sizes; (void)n_in; (void)out_size;
    const float* x   = (const float*)d_in[0];
    const float* w1  = (const float*)d_in[1];
    const float* b1  = (const float*)d_in[2];
    const float* g1  = (const float*)d_in[3];
    const float* be1 = (const float*)d_in[4];
    const float* w2  = (const float*)d_in[5];
    const float* b2  = (const float*)d_in[6];
    const float* g2  = (const float*)d_in[7];
    const float* be2 = (const float*)d_in[8];
    const float* wf  = (const float*)d_in[9];
    const float* bf  = (const float*)d_in[10];
    const float* gf  = (const float*)d_in[11];
    const float* bef = (const float*)d_in[12];
    float* out = (float*)d_out;

    cudaFuncSetAttribute(att_kernel, cudaFuncAttributeMaxDynamicSharedMemorySize,
                         ATT_SMEM_BYTES);
    cudaFuncSetAttribute(mma_gemm_kernel<__half>,
                         cudaFuncAttributeMaxDynamicSharedMemorySize, GEMM_SMEM_BYTES);
    cudaFuncSetAttribute(mma_gemm_kernel<float>,
                         cudaFuncAttributeMaxDynamicSharedMemorySize, GEMM_SMEM_BYTES);

    __half *y1p, *y2p;
    cudaGetSymbolAddress((void**)&y1p, g_y1h);
    cudaGetSymbolAddress((void**)&y2p, g_y2h);
    __nv_bfloat16 *xh, *xl, *ph, *pl, *wh, *wl, *wfh, *wfl;
    cudaGetSymbolAddress((void**)&xh,  g_xh);
    cudaGetSymbolAddress((void**)&xl,  g_xl);
    cudaGetSymbolAddress((void**)&ph,  g_ph);
    cudaGetSymbolAddress((void**)&pl,  g_pl);
    cudaGetSymbolAddress((void**)&wh,  g_wh);
    cudaGetSymbolAddress((void**)&wl,  g_wl);
    cudaGetSymbolAddress((void**)&wfh, g_wfh);
    cudaGetSymbolAddress((void**)&wfl, g_wfl);

    conv_all_kernel<<<CONV_X_BLOCKS + CONV_W_BLOCKS, 256>>>(x, w1, w2, wf);

    // dual GEMM: stacked M=512 (rows 0-255 -> w1/y1, 256-511 -> w2/y2), fp16 out
    dim3 gd(4, NL / 128, NB);
    mma_gemm_kernel<__half><<<gd, 256, GEMM_SMEM_BYTES>>>(
        wh, wl, wh + NC * NC, wl + NC * NC, b1, b2, xh, xl, y1p, y2p, 256);
    bn_stats12_kernel<<<2 * NC, 1024>>>(g1, be1, g2, be2);
    att_kernel<<<NB * NC, ATT_THREADS, ATT_SMEM_BYTES>>>(x);
    // final GEMM: M=256 single matrix, fp32 out
    dim3 gf2(2, NL / 128, NB);
    mma_gemm_kernel<float><<<gf2, 256, GEMM_SMEM_BYTES>>>(
        wfh, wfl, wfh, wfl, bf, bf, ph, pl, out, out, 512);
    bn_statsF_relu_kernel<<<NO, 1024>>>(out, gf, bef);
}

// round 14
// speedup vs baseline: 1.0554x; 1.0051x over previous
#include <cuda_runtime.h>
#include <cuda_bf16.h>
#include <cuda_fp16.h>
#include <stdint.h>

#define NB 4
#define NC 256
#define NO 256
#define NL 4096          // H*W
#define NEPS 1e-5f
#define LOG2E 1.4426950408889634f

#define ATT_THREADS 1024
// smem: t12 8712 f32 (66x66 float2) | xs 4488 f32 (66x68 padded) | w 36864 f16
#define ATT_F_T12  0
#define ATT_F_XS   8712
#define ATT_F_WH   (8712 + 4488)                 // float-slot offset of fp16 w plane
#define ATT_SMEM_BYTES ((8712 + 4488) * 4 + 36864 * 2)   // 126528 B

#define EX2_APPROX(d, a) \
    asm("ex2.approx.ftz.f32 %0, %1;" : "=f"(d) : "f"(a))

// ---- tensor-core helpers (canonical m16n8k16 bf16 fragments) ----
#define LDSM_X4(r, a) \
    asm volatile("ldmatrix.sync.aligned.m8n8.x4.shared.b16 {%0,%1,%2,%3}, [%4];" \
        : "=r"((r)[0]), "=r"((r)[1]), "=r"((r)[2]), "=r"((r)[3]) : "r"(a))
#define LDSM_X4_T(r, a) \
    asm volatile("ldmatrix.sync.aligned.m8n8.x4.trans.shared.b16 {%0,%1,%2,%3}, [%4];" \
        : "=r"((r)[0]), "=r"((r)[1]), "=r"((r)[2]), "=r"((r)[3]) : "r"(a))
#define MMA_BF16(c, a, b0_, b1_) \
    asm volatile("mma.sync.aligned.m16n8k16.row.col.f32.bf16.bf16.f32 " \
        "{%0,%1,%2,%3}, {%4,%5,%6,%7}, {%8,%9}, {%0,%1,%2,%3};" \
        : "+f"((c)[0]), "+f"((c)[1]), "+f"((c)[2]), "+f"((c)[3]) \
        : "r"((a)[0]), "r"((a)[1]), "r"((a)[2]), "r"((a)[3]), "r"(b0_), "r"(b1_))

__device__ __forceinline__ uint32_t cvta_smem(const void* p) {
    return (uint32_t)__cvta_generic_to_shared(p);
}

// ---------------- scratch (static device globals; no runtime allocs) ----------------
static __device__ __half g_y1h[NB*NC*NL];
static __device__ __half g_y2h[NB*NC*NL];
static __device__ __nv_bfloat16 g_xh[NB*NC*NL],  g_xl[NB*NC*NL];
static __device__ __nv_bfloat16 g_ph[NB*NC*NL],  g_pl[NB*NC*NL];
static __device__ __nv_bfloat16 g_wh[2*NC*NC],   g_wl[2*NC*NC];     // w1 | w2 stacked
static __device__ __nv_bfloat16 g_wfh[NO*NC],    g_wfl[NO*NC];
static __device__ float g_sc1[NC], g_sh1[NC];
static __device__ float g_sc2[NC], g_sh2[NC];

// ---------------- fp32 -> bf16 hi/lo conversion (x and all weights, one launch) -----
__device__ __forceinline__ void split2(const float a, const float b,
                                       __nv_bfloat162* dh, __nv_bfloat162* dl)
{
    __nv_bfloat16 ha = __float2bfloat16(a), hb = __float2bfloat16(b);
    __nv_bfloat16 la = __float2bfloat16(a - __bfloat162float(ha));
    __nv_bfloat16 lb = __float2bfloat16(b - __bfloat162float(hb));
    *dh = __halves2bfloat162(ha, hb);
    *dl = __halves2bfloat162(la, lb);
}

#define CONV_X_BLOCKS ((NB*NC*NL) / (256 * 4))      // 16384
#define CONV_W_BLOCKS ((3*NC*NC) / (256 * 4))       // 192

__global__ __launch_bounds__(256) void conv_all_kernel(
    const float* __restrict__ x,
    const float* __restrict__ w1, const float* __restrict__ w2,
    const float* __restrict__ wf)
{
    if (blockIdx.x < CONV_X_BLOCKS) {
        const int i = (blockIdx.x * 256 + threadIdx.x) * 4;
        float4 v = *(const float4*)&x[i];
        split2(v.x, v.y, (__nv_bfloat162*)&g_xh[i],     (__nv_bfloat162*)&g_xl[i]);
        split2(v.z, v.w, (__nv_bfloat162*)&g_xh[i + 2], (__nv_bfloat162*)&g_xl[i + 2]);
    } else {
        const int i = ((blockIdx.x - CONV_X_BLOCKS) * 256 + threadIdx.x) * 4;
        float4 v;
        __nv_bfloat162 *dh, *dl;
        if (i < 65536)       { v = *(const float4*)&w1[i];          dh = (__nv_bfloat162*)&g_wh[i];  dl = (__nv_bfloat162*)&g_wl[i]; }
        else if (i < 131072) { v = *(const float4*)&w2[i - 65536];  dh = (__nv_bfloat162*)&g_wh[i];  dl = (__nv_bfloat162*)&g_wl[i]; }
        else                 { v = *(const float4*)&wf[i - 131072]; dh = (__nv_bfloat162*)&g_wfh[i - 131072]; dl = (__nv_bfloat162*)&g_wfl[i - 131072]; }
        split2(v.x, v.y, dh,     dl);
        split2(v.z, v.w, dh + 1, dl + 1);
    }
}

// ---------------- bf16x3 tensor-core GEMM (pre-split, smem double-buffered) ---------
#define APAD 40
#define BPAD 136
#define A_ELT (128 * APAD)     // 5120 bf16 per A buffer
#define B_ELT (32 * BPAD)      // 4352 bf16 per B buffer
#define GEMM_SMEM_BYTES ((2 * A_ELT * 2 + 2 * B_ELT * 2) * 2)   // 75776 B

template <typename OutT>
__global__ __launch_bounds__(256) void mma_gemm_kernel(
    const __nv_bfloat16* __restrict__ Ah0, const __nv_bfloat16* __restrict__ Al0,
    const __nv_bfloat16* __restrict__ Ah1, const __nv_bfloat16* __restrict__ Al1,
    const float* __restrict__ bias0, const float* __restrict__ bias1,
    const __nv_bfloat16* __restrict__ Bh, const __nv_bfloat16* __restrict__ Bl,
    OutT* __restrict__ Y0, OutT* __restrict__ Y1, int Mhalf)
{
    extern __shared__ __align__(16) __nv_bfloat16 gsm[];
    __nv_bfloat16* sAh = gsm;                      // [2][128][APAD]
    __nv_bfloat16* sAl = sAh + 2 * A_ELT;
    __nv_bfloat16* sBh = sAl + 2 * A_ELT;          // [2][32][BPAD]
    __nv_bfloat16* sBl = sBh + 2 * B_ELT;

    const int tid  = threadIdx.x;
    const int lane = tid & 31;
    const int wid  = tid >> 5;
    const int wm   = wid >> 2;
    const int wn   = wid & 3;
    const int b    = blockIdx.z;
    const int l0   = blockIdx.y * 128;
    const int o0   = blockIdx.x * 128;

    const __nv_bfloat16 *Ah, *Al; const float* bi; OutT* Yb; int row0;
    if (o0 < Mhalf) { Ah = Ah0; Al = Al0; bi = bias0; Yb = Y0; row0 = o0; }
    else            { Ah = Ah1; Al = Al1; bi = bias1; Yb = Y1; row0 = o0 - Mhalf; }
    Ah += (size_t)row0 * NC;  Al += (size_t)row0 * NC;  bi += row0;
    const __nv_bfloat16* Bhb = Bh + (size_t)b * NC * NL + l0;
    const __nv_bfloat16* Blb = Bl + (size_t)b * NC * NL + l0;
    Yb += ((size_t)b * NO + row0) * NL + l0;

    const int ar = tid >> 1, ka  = (tid & 1) * 16;   // A: 2 thr/row, 16 bf16 each
    const int br = tid >> 3, blc = (tid & 7) * 16;   // B: 8 thr/row, 16 bf16 each
    const int aoff = ar * APAD + ka;
    const int boff = br * BPAD + blc;

    uint4 pah[2], pal[2], pbh[2], pbl[2];
    pah[0] = *(const uint4*)&Ah[(size_t)ar * NC + ka];
    pah[1] = *(const uint4*)&Ah[(size_t)ar * NC + ka + 8];
    pal[0] = *(const uint4*)&Al[(size_t)ar * NC + ka];
    pal[1] = *(const uint4*)&Al[(size_t)ar * NC + ka + 8];
    pbh[0] = *(const uint4*)&Bhb[(size_t)br * NL + blc];
    pbh[1] = *(const uint4*)&Bhb[(size_t)br * NL + blc + 8];
    pbl[0] = *(const uint4*)&Blb[(size_t)br * NL + blc];
    pbl[1] = *(const uint4*)&Blb[(size_t)br * NL + blc + 8];

    float acc[4][4][4];
#pragma unroll
    for (int i = 0; i < 4; i++)
#pragma unroll
        for (int j = 0; j < 4; j++)
#pragma unroll
            for (int r = 0; r < 4; r++) acc[i][j][r] = 0.f;

    const int a_row = wm * 64 + (lane & 15);
    const int a_col = (lane >> 4) * 8;
    const uint32_t aAh = cvta_smem(&sAh[a_row * APAD + a_col]);
    const uint32_t aAl = cvta_smem(&sAl[a_row * APAD + a_col]);
    const int b_row = (lane & 15);
    const int b_col = wn * 32 + (lane >> 4) * 8;
    const uint32_t aBh = cvta_smem(&sBh[b_row * BPAD + b_col]);
    const uint32_t aBl = cvta_smem(&sBl[b_row * BPAD + b_col]);

#pragma unroll 1
    for (int ch = 0; ch < 8; ch++) {
        const int q = ch & 1;
        const uint32_t qa = (uint32_t)(q * A_ELT * 2);
        const uint32_t qb = (uint32_t)(q * B_ELT * 2);
        *(uint4*)&sAh[q * A_ELT + aoff]      = pah[0];
        *(uint4*)&sAh[q * A_ELT + aoff + 8]  = pah[1];
        *(uint4*)&sAl[q * A_ELT + aoff]      = pal[0];
        *(uint4*)&sAl[q * A_ELT + aoff + 8]  = pal[1];
        *(uint4*)&sBh[q * B_ELT + boff]      = pbh[0];
        *(uint4*)&sBh[q * B_ELT + boff + 8]  = pbh[1];
        *(uint4*)&sBl[q * B_ELT + boff]      = pbl[0];
        *(uint4*)&sBl[q * B_ELT + boff + 8]  = pbl[1];
        __syncthreads();

        if (ch < 7) {
            const int k0 = (ch + 1) * 32;
            pah[0] = *(const uint4*)&Ah[(size_t)ar * NC + k0 + ka];
            pah[1] = *(const uint4*)&Ah[(size_t)ar * NC + k0 + ka + 8];
            pal[0] = *(const uint4*)&Al[(size_t)ar * NC + k0 + ka];
            pal[1] = *(const uint4*)&Al[(size_t)ar * NC + k0 + ka + 8];
            pbh[0] = *(const uint4*)&Bhb[(size_t)(k0 + br) * NL + blc];
            pbh[1] = *(const uint4*)&Bhb[(size_t)(k0 + br) * NL + blc + 8];
            pbl[0] = *(const uint4*)&Blb[(size_t)(k0 + br) * NL + blc];
            pbl[1] = *(const uint4*)&Blb[(size_t)(k0 + br) * NL + blc + 8];
        }

#pragma unroll
        for (int h = 0; h < 2; h++) {
            uint32_t bh[8], bl[8];
#pragma unroll
            for (int nt = 0; nt < 2; nt++) {
                const uint32_t off = (uint32_t)((h * 16) * BPAD + nt * 16) * 2;
                LDSM_X4_T(&bh[nt * 4], aBh + qb + off);
                LDSM_X4_T(&bl[nt * 4], aBl + qb + off);
            }
#pragma unroll
            for (int i = 0; i < 4; i++) {
                uint32_t ah[4], al[4];
                const uint32_t off = (uint32_t)((i * 16) * APAD + h * 16) * 2;
                LDSM_X4(ah, aAh + qa + off);
                LDSM_X4(al, aAl + qa + off);
#pragma unroll
                for (int j = 0; j < 4; j++) {
                    MMA_BF16(acc[i][j], ah, bh[j * 2], bh[j * 2 + 1]);
                    MMA_BF16(acc[i][j], ah, bl[j * 2], bl[j * 2 + 1]);
                    MMA_BF16(acc[i][j], al, bh[j * 2], bh[j * 2 + 1]);
                }
            }
        }
    }

    const int g   = lane >> 2;
    const int tig = lane & 3;
#pragma unroll
    for (int i = 0; i < 4; i++) {
        const int r0 = wm * 64 + i * 16 + g;
        const float bi0 = bi[r0];
        const float bi8 = bi[r0 + 8];
        OutT* y0 = Yb + (size_t)r0 * NL + wn * 32 + tig * 2;
        OutT* y8 = y0 + (size_t)8 * NL;
#pragma unroll
        for (int j = 0; j < 4; j++) {
            if (sizeof(OutT) == 2) {
                *(__half2*)&y0[j * 8] = __floats2half2_rn(acc[i][j][0] + bi0, acc[i][j][1] + bi0);
                *(__half2*)&y8[j * 8] = __floats2half2_rn(acc[i][j][2] + bi8, acc[i][j][3] + bi8);
            } else {
                *(float2*)&y0[j * 8] = make_float2(acc[i][j][0] + bi0, acc[i][j][1] + bi0);
                *(float2*)&y8[j * 8] = make_float2(acc[i][j][2] + bi8, acc[i][j][3] + bi8);
            }
        }
    }
}

// ---------------- BN stats (1024 thr, shuffle reduce) ----------------
__device__ __forceinline__ void warp_red2(float& s, float& s2)
{
#pragma unroll
    for (int o = 16; o > 0; o >>= 1) {
        s  += __shfl_xor_sync(0xFFFFFFFFu, s,  o);
        s2 += __shfl_xor_sync(0xFFFFFFFFu, s2, o);
    }
}

__global__ __launch_bounds__(1024) void bn_stats12_kernel(
    const float* __restrict__ g1, const float* __restrict__ be1,
    const float* __restrict__ g2, const float* __restrict__ be2)
{
    const int ch = blockIdx.x & (NC - 1);
    const bool first = blockIdx.x < NC;
    const __half* y = first ? g_y1h : g_y2h;
    float s = 0.f, s2 = 0.f;
#pragma unroll
    for (int k = 0; k < 2; k++) {
        const int i = (threadIdx.x + k * 1024) * 8;      // 8 halves per load
        const int b = i >> 12, l = i & (NL - 1);
        const uint4 u = *(const uint4*)&y[((size_t)b * NC + ch) * NL + l];
        const __half2* hp = (const __half2*)&u;
#pragma unroll
        for (int t = 0; t < 4; t++) {
            float2 f = __half22float2(hp[t]);
            s  += f.x + f.y;
            s2 += fmaf(f.x, f.x, f.y * f.y);
        }
    }
    warp_red2(s, s2);
    __shared__ float rs[32], rq[32];
    const int lane = threadIdx.x & 31, wid = threadIdx.x >> 5;
    if (lane == 0) { rs[wid] = s; rq[wid] = s2; }
    __syncthreads();
    if (wid == 0) {
        s = rs[lane]; s2 = rq[lane];
        warp_red2(s, s2);
        if (lane == 0) {
            const float inv = 1.f / (float)(NB * NL);
            float mu  = s * inv;
            float var = s2 * inv - mu * mu;
            float gwv = first ? g1[ch] : g2[ch];
            float bwv = first ? be1[ch] : be2[ch];
            float r   = rsqrtf(var + NEPS) * gwv;
            if (first) { g_sc1[ch] = r; g_sh1[ch] = bwv - mu * r; }
            else       { g_sc2[ch] = r; g_sh2[ch] = bwv - mu * r; }
        }
    }
}

__global__ __launch_bounds__(1024) void bn_statsF_relu_kernel(
    float* __restrict__ y,
    const float* __restrict__ gw, const float* __restrict__ bw)
{
    const int ch = blockIdx.x;
    float4 vv[4];
    size_t addr[4];
    float s = 0.f, s2 = 0.f;
#pragma unroll
    for (int k = 0; k < 4; k++) {
        const int i = (threadIdx.x + k * 1024) * 4;
        const int b = i >> 12, l = i & (NL - 1);
        addr[k] = ((size_t)b * NO + ch) * NL + l;
        float4 v = *(const float4*)&y[addr[k]];
        vv[k] = v;
        s  += (v.x + v.y) + (v.z + v.w);
        s2 += fmaf(v.x, v.x, v.y * v.y) + fmaf(v.z, v.z, v.w * v.w);
    }
    warp_red2(s, s2);
    __shared__ float rs[32], rq[32];
    __shared__ float bcast[2];
    const int lane = threadIdx.x & 31, wid = threadIdx.x >> 5;
    if (lane == 0) { rs[wid] = s; rq[wid] = s2; }
    __syncthreads();
    if (wid == 0) {
        s = rs[lane]; s2 = rq[lane];
        warp_red2(s, s2);
        if (lane == 0) {
            const float inv = 1.f / (float)(NB * NL);
            float mu  = s * inv;
            float var = s2 * inv - mu * mu;
            float r   = rsqrtf(var + NEPS) * gw[ch];
            bcast[0] = r;
            bcast[1] = bw[ch] - mu * r;
        }
    }
    __syncthreads();
    const float sc = bcast[0], sh = bcast[1];
#pragma unroll
    for (int k = 0; k < 4; k++) {
        float4 v = vv[k];
        v.x = fmaxf(fmaf(v.x, sc, sh), 0.f);
        v.y = fmaxf(fmaf(v.y, sc, sh), 0.f);
        v.z = fmaxf(fmaf(v.z, sc, sh), 0.f);
        v.w = fmaxf(fmaf(v.w, sc, sh), 0.f);
        *(float4*)&y[addr[k]] = v;
    }
}

// ---------------- scrambled-unfold attention: fp16 weight plane ----------------------
// Phase 1 writes softmax weights (fp16) into smem; no max-subtraction (logits >= 0).
// Phase 2: vectorized weighted gather (xs pitch 68 -> 16B-aligned float4 tap loads).
__global__ __launch_bounds__(ATT_THREADS, 1) void att_kernel(const float* __restrict__ x)
{
    extern __shared__ float sm[];
    float*  t12 = sm + ATT_F_T12;            // 66x66 interleaved (tri1, tri2) float2
    float*  xs  = sm + ATT_F_XS;             // 66x68 padded x plane (16B-aligned rows)
    __half* wsm = (__half*)(sm + ATT_F_WH);  // 36864 fp16 softmax weights

    const int bc = blockIdx.x;
    const int c  = bc & (NC - 1);
    const size_t base = (size_t)bc * NL;
    const float sc1 = g_sc1[c], sh1 = g_sh1[c];
    const float sc2 = g_sc2[c], sh2 = g_sh2[c];

    for (int i = threadIdx.x; i < 4488; i += ATT_THREADS) xs[i] = 0.f;
    for (int i = threadIdx.x; i < 8712; i += ATT_THREADS) t12[i] = 0.f;
    __syncthreads();

    {
        const int l4 = threadIdx.x * 4;      // exactly covers 0..4092
        float4 xv = *(const float4*)&x[base + l4];
        const __half2* ap = (const __half2*)(g_y1h + base + l4);
        const __half2* qp = (const __half2*)(g_y2h + base + l4);
        float2 a01 = __half22float2(ap[0]), a23 = __half22float2(ap[1]);
        float2 q01 = __half22float2(qp[0]), q23 = __half22float2(qp[1]);
        const int xidx = (l4 >> 6) * 68 + (l4 & 63) + 69;   // (row+1)*68 + col+1
        xs[xidx+0] = xv.x; xs[xidx+1] = xv.y; xs[xidx+2] = xv.z; xs[xidx+3] = xv.w;
        const int pidx = (l4 >> 6) * 66 + (l4 & 63) + 67;   // t12 keeps 66 pitch
        float t1v[4] = {
            fmaxf(fmaf(a01.x, sc1, sh1), 0.f), fmaxf(fmaf(a01.y, sc1, sh1), 0.f),
            fmaxf(fmaf(a23.x, sc1, sh1), 0.f), fmaxf(fmaf(a23.y, sc1, sh1), 0.f) };
        float t2v[4] = {
            fmaxf(fmaf(q01.x, sc2, sh2), 0.f), fmaxf(fmaf(q01.y, sc2, sh2), 0.f),
            fmaxf(fmaf(q23.x, sc2, sh2), 0.f), fmaxf(fmaf(q23.y, sc2, sh2), 0.f) };
#pragma unroll
        for (int j = 0; j < 4; j++)
            *(float2*)&t12[2 * (pidx + j)] = make_float2(t1v[j], t2v[j]);
    }
    __syncthreads();

    // phase 1: per group (9 consecutive n), emit the 9 softmax weights (fp16)
    for (int g = threadIdx.x; g < NL; g += ATT_THREADS) {
        const int n0 = 9 * g;
        const int p0 = n0 >> 12;
        const int l0 = n0 & (NL - 1);
        const int di0 = (p0 * 171) >> 9, dj0 = p0 - 3 * di0;
        const int p1 = p0 + 1;
        const int di1 = (p1 * 171) >> 9, dj1 = p1 - 3 * di1;
        const int C0 = di0 * 66 + dj0;
        const int C1 = di1 * 66 + dj1 - 4224;
        float ku[9], qu[9];
#pragma unroll
        for (int r = 0; r < 9; r++) {
            const int l = l0 + r;
            const int C = (l >> 12) ? C1 : C0;
            const int idx = (l >> 6) * 66 + (l & 63) + C;
            const float2 kq = *(const float2*)&t12[2 * idx];
            ku[r] = kq.x; qu[r] = kq.y;
        }
        const float quC = qu[4] * LOG2E;
        const float kuC = ku[4] * LOG2E;
        float e[9];
        float s = 0.f;
#pragma unroll
        for (int r = 0; r < 9; r++) {
            const float lg = fmaf(ku[r], quC, kuC * qu[r]);
            EX2_APPROX(e[r], lg);
            s += e[r];
        }
        const float inv = __fdividef(1.f, s);
#pragma unroll
        for (int r = 0; r < 9; r++)
            wsm[n0 + r] = __float2half_rn(e[r] * inv);
    }
    __syncthreads();

    // phase 2: weighted gather; xs taps via float4/float2, w via 8B fp16 loads
    {
        const int l4  = threadIdx.x * 4;
        const int row = l4 >> 6, col = l4 & 63;
        float acc[4] = {0.f, 0.f, 0.f, 0.f};
#pragma unroll
        for (int tr = 0; tr < 3; tr++) {
            const int pb = (row + tr) * 68 + col;     // 16B-aligned
            const float4 x03 = *(const float4*)&xs[pb];
            const float2 x45 = *(const float2*)&xs[pb + 4];
            const float xv[6] = {x03.x, x03.y, x03.z, x03.w, x45.x, x45.y};
#pragma unroll
            for (int dj = 0; dj < 3; dj++) {
                const int p = tr * 3 + dj;
                const uint2 wu = *(const uint2*)&wsm[(p << 12) + l4];
                const float2 w01 = __half22float2(*(const __half2*)&wu.x);
                const float2 w23 = __half22float2(*(const __half2*)&wu.y);
                acc[0] = fmaf(w01.x, xv[dj + 0], acc[0]);
                acc[1] = fmaf(w01.y, xv[dj + 1], acc[1]);
                acc[2] = fmaf(w23.x, xv[dj + 2], acc[2]);
                acc[3] = fmaf(w23.y, xv[dj + 3], acc[3]);
            }
        }
        uint32_t oh, ol, oh2, ol2;
        {
            __nv_bfloat16 h0 = __float2bfloat16(acc[0]);
            __nv_bfloat16 h1 = __float2bfloat16(acc[1]);
            __nv_bfloat16 l0b = __float2bfloat16(acc[0] - __bfloat162float(h0));
            __nv_bfloat16 l1b = __float2bfloat16(acc[1] - __bfloat162float(h1));
            __nv_bfloat162 ph = __halves2bfloat162(h0, h1);
            __nv_bfloat162 pl = __halves2bfloat162(l0b, l1b);
            oh = *(uint32_t*)&ph; ol = *(uint32_t*)&pl;
        }
        {
            __nv_bfloat16 h2 = __float2bfloat16(acc[2]);
            __nv_bfloat16 h3 = __float2bfloat16(acc[3]);
            __nv_bfloat16 l2b = __float2bfloat16(acc[2] - __bfloat162float(h2));
            __nv_bfloat16 l3b = __float2bfloat16(acc[3] - __bfloat162float(h3));
            __nv_bfloat162 ph = __halves2bfloat162(h2, h3);
            __nv_bfloat162 pl = __halves2bfloat162(l2b, l3b);
            oh2 = *(uint32_t*)&ph; ol2 = *(uint32_t*)&pl;
        }
        *(uint2*)&g_ph[base + l4] = make_uint2(oh, oh2);
        *(uint2*)&g_pl[base + l4] = make_uint2(ol, ol2);
    }
}

// ---------------- launch ----------------
extern "C" void kernel_launch(void* const* d_in, const int* in_sizes, int n_in,
                              void* d_out, int out_size)
{
    (void)in_sizes; (void)n_in; (void)out_size;
    const float* x   = (const float*)d_in[0];
    const float* w1  = (const float*)d_in[1];
    const float* b1  = (const float*)d_in[2];
    const float* g1  = (const float*)d_in[3];
    const float* be1 = (const float*)d_in[4];
    const float* w2  = (const float*)d_in[5];
    const float* b2  = (const float*)d_in[6];
    const float* g2  = (const float*)d_in[7];
    const float* be2 = (const float*)d_in[8];
    const float* wf  = (const float*)d_in[9];
    const float* bf  = (const float*)d_in[10];
    const float* gf  = (const float*)d_in[11];
    const float* bef = (const float*)d_in[12];
    float* out = (float*)d_out;

    cudaFuncSetAttribute(att_kernel, cudaFuncAttributeMaxDynamicSharedMemorySize,
                         ATT_SMEM_BYTES);
    cudaFuncSetAttribute(mma_gemm_kernel<__half>,
                         cudaFuncAttributeMaxDynamicSharedMemorySize, GEMM_SMEM_BYTES);
    cudaFuncSetAttribute(mma_gemm_kernel<float>,
                         cudaFuncAttributeMaxDynamicSharedMemorySize, GEMM_SMEM_BYTES);

    __half *y1p, *y2p;
    cudaGetSymbolAddress((void**)&y1p, g_y1h);
    cudaGetSymbolAddress((void**)&y2p, g_y2h);
    __nv_bfloat16 *xh, *xl, *ph, *pl, *wh, *wl, *wfh, *wfl;
    cudaGetSymbolAddress((void**)&xh,  g_xh);
    cudaGetSymbolAddress((void**)&xl,  g_xl);
    cudaGetSymbolAddress((void**)&ph,  g_ph);
    cudaGetSymbolAddress((void**)&pl,  g_pl);
    cudaGetSymbolAddress((void**)&wh,  g_wh);
    cudaGetSymbolAddress((void**)&wl,  g_wl);
    cudaGetSymbolAddress((void**)&wfh, g_wfh);
    cudaGetSymbolAddress((void**)&wfl, g_wfl);

    conv_all_kernel<<<CONV_X_BLOCKS + CONV_W_BLOCKS, 256>>>(x, w1, w2, wf);

    // dual GEMM: stacked M=512 (rows 0-255 -> w1/y1, 256-511 -> w2/y2), fp16 out
    dim3 gd(4, NL / 128, NB);
    mma_gemm_kernel<__half><<<gd, 256, GEMM_SMEM_BYTES>>>(
        wh, wl, wh + NC * NC, wl + NC * NC, b1, b2, xh, xl, y1p, y2p, 256);
    bn_stats12_kernel<<<2 * NC, 1024>>>(g1, be1, g2, be2);
    att_kernel<<<NB * NC, ATT_THREADS, ATT_SMEM_BYTES>>>(x);
    // final GEMM: M=256 single matrix, fp32 out
    dim3 gf2(2, NL / 128, NB);
    mma_gemm_kernel<float><<<gf2, 256, GEMM_SMEM_BYTES>>>(
        wfh, wfl, wfh, wfl, bf, bf, ph, pl, out, out, 512);
    bn_statsF_relu_kernel<<<NO, 1024>>>(out, gf, bef);
}

// round 17
// speedup vs baseline: 1.0696x; 1.0134x over previous
#include <cuda_runtime.h>
#include <cuda_bf16.h>
#include <cuda_fp16.h>
#include <stdint.h>

#define NB 4
#define NC 256
#define NO 256
#define NL 4096          // H*W
#define NEPS 1e-5f
#define LOG2E 1.4426950408889634f

#define ATT_THREADS 1024
// smem: t12 8712 f32 (66x66 float2) | xs 4488 f32 (66x68 padded) | w 36864 f16
#define ATT_F_T12  0
#define ATT_F_XS   8712
#define ATT_F_WH   (8712 + 4488)                 // float-slot offset of fp16 w plane
#define ATT_SMEM_BYTES ((8712 + 4488) * 4 + 36864 * 2)   // 126528 B

#define EX2_APPROX(d, a) \
    asm("ex2.approx.ftz.f32 %0, %1;" : "=f"(d) : "f"(a))

// ---- tensor-core helpers (canonical m16n8k16 bf16 fragments) ----
#define LDSM_X4(r, a) \
    asm volatile("ldmatrix.sync.aligned.m8n8.x4.shared.b16 {%0,%1,%2,%3}, [%4];" \
        : "=r"((r)[0]), "=r"((r)[1]), "=r"((r)[2]), "=r"((r)[3]) : "r"(a))
#define LDSM_X4_T(r, a) \
    asm volatile("ldmatrix.sync.aligned.m8n8.x4.trans.shared.b16 {%0,%1,%2,%3}, [%4];" \
        : "=r"((r)[0]), "=r"((r)[1]), "=r"((r)[2]), "=r"((r)[3]) : "r"(a))
#define MMA_BF16(c, a, b0_, b1_) \
    asm volatile("mma.sync.aligned.m16n8k16.row.col.f32.bf16.bf16.f32 " \
        "{%0,%1,%2,%3}, {%4,%5,%6,%7}, {%8,%9}, {%0,%1,%2,%3};" \
        : "+f"((c)[0]), "+f"((c)[1]), "+f"((c)[2]), "+f"((c)[3]) \
        : "r"((a)[0]), "r"((a)[1]), "r"((a)[2]), "r"((a)[3]), "r"(b0_), "r"(b1_))

__device__ __forceinline__ uint32_t cvta_smem(const void* p) {
    return (uint32_t)__cvta_generic_to_shared(p);
}

// ---------------- scratch (static device globals; no runtime allocs) ----------------
static __device__ __half g_y1h[NB*NC*NL];
static __device__ __half g_y2h[NB*NC*NL];
static __device__ __nv_bfloat16 g_xh[NB*NC*NL],  g_xl[NB*NC*NL];
static __device__ __nv_bfloat16 g_ph[NB*NC*NL],  g_pl[NB*NC*NL];
static __device__ __nv_bfloat16 g_wh[2*NC*NC],   g_wl[2*NC*NC];     // w1 | w2 stacked
static __device__ __nv_bfloat16 g_wfh[NO*NC],    g_wfl[NO*NC];
static __device__ float g_sc1[NC], g_sh1[NC];
static __device__ float g_sc2[NC], g_sh2[NC];

// ---------------- fp32 -> bf16 hi/lo conversion (x and all weights, one launch) -----
__device__ __forceinline__ void split2(const float a, const float b,
                                       __nv_bfloat162* dh, __nv_bfloat162* dl)
{
    __nv_bfloat16 ha = __float2bfloat16(a), hb = __float2bfloat16(b);
    __nv_bfloat16 la = __float2bfloat16(a - __bfloat162float(ha));
    __nv_bfloat16 lb = __float2bfloat16(b - __bfloat162float(hb));
    *dh = __halves2bfloat162(ha, hb);
    *dl = __halves2bfloat162(la, lb);
}

#define CONV_X_BLOCKS ((NB*NC*NL) / (256 * 4))      // 16384
#define CONV_W_BLOCKS ((3*NC*NC) / (256 * 4))       // 192

__global__ __launch_bounds__(256) void conv_all_kernel(
    const float* __restrict__ x,
    const float* __restrict__ w1, const float* __restrict__ w2,
    const float* __restrict__ wf)
{
    if (blockIdx.x < CONV_X_BLOCKS) {
        const int i = (blockIdx.x * 256 + threadIdx.x) * 4;
        float4 v = *(const float4*)&x[i];
        split2(v.x, v.y, (__nv_bfloat162*)&g_xh[i],     (__nv_bfloat162*)&g_xl[i]);
        split2(v.z, v.w, (__nv_bfloat162*)&g_xh[i + 2], (__nv_bfloat162*)&g_xl[i + 2]);
    } else {
        const int i = ((blockIdx.x - CONV_X_BLOCKS) * 256 + threadIdx.x) * 4;
        float4 v;
        __nv_bfloat162 *dh, *dl;
        if (i < 65536)       { v = *(const float4*)&w1[i];          dh = (__nv_bfloat162*)&g_wh[i];  dl = (__nv_bfloat162*)&g_wl[i]; }
        else if (i < 131072) { v = *(const float4*)&w2[i - 65536];  dh = (__nv_bfloat162*)&g_wh[i];  dl = (__nv_bfloat162*)&g_wl[i]; }
        else                 { v = *(const float4*)&wf[i - 131072]; dh = (__nv_bfloat162*)&g_wfh[i - 131072]; dl = (__nv_bfloat162*)&g_wfl[i - 131072]; }
        split2(v.x, v.y, dh,     dl);
        split2(v.z, v.w, dh + 1, dl + 1);
    }
}

// ---------------- bf16x3 tensor-core GEMM (pre-split, smem double-buffered) ---------
#define APAD 40
#define BPAD 136
#define A_ELT (128 * APAD)     // 5120 bf16 per A buffer
#define B_ELT (32 * BPAD)      // 4352 bf16 per B buffer
#define GEMM_SMEM_BYTES ((2 * A_ELT * 2 + 2 * B_ELT * 2) * 2)   // 75776 B

template <typename OutT>
__global__ __launch_bounds__(256) void mma_gemm_kernel(
    const __nv_bfloat16* __restrict__ Ah0, const __nv_bfloat16* __restrict__ Al0,
    const __nv_bfloat16* __restrict__ Ah1, const __nv_bfloat16* __restrict__ Al1,
    const float* __restrict__ bias0, const float* __restrict__ bias1,
    const __nv_bfloat16* __restrict__ Bh, const __nv_bfloat16* __restrict__ Bl,
    OutT* __restrict__ Y0, OutT* __restrict__ Y1, int Mhalf)
{
    extern __shared__ __align__(16) __nv_bfloat16 gsm[];
    __nv_bfloat16* sAh = gsm;                      // [2][128][APAD]
    __nv_bfloat16* sAl = sAh + 2 * A_ELT;
    __nv_bfloat16* sBh = sAl + 2 * A_ELT;          // [2][32][BPAD]
    __nv_bfloat16* sBl = sBh + 2 * B_ELT;

    const int tid  = threadIdx.x;
    const int lane = tid & 31;
    const int wid  = tid >> 5;
    const int wm   = wid >> 2;
    const int wn   = wid & 3;
    const int b    = blockIdx.z;
    const int l0   = blockIdx.y * 128;
    const int o0   = blockIdx.x * 128;

    const __nv_bfloat16 *Ah, *Al; const float* bi; OutT* Yb; int row0;
    if (o0 < Mhalf) { Ah = Ah0; Al = Al0; bi = bias0; Yb = Y0; row0 = o0; }
    else            { Ah = Ah1; Al = Al1; bi = bias1; Yb = Y1; row0 = o0 - Mhalf; }
    Ah += (size_t)row0 * NC;  Al += (size_t)row0 * NC;  bi += row0;
    const __nv_bfloat16* Bhb = Bh + (size_t)b * NC * NL + l0;
    const __nv_bfloat16* Blb = Bl + (size_t)b * NC * NL + l0;
    Yb += ((size_t)b * NO + row0) * NL + l0;

    const int ar = tid >> 1, ka  = (tid & 1) * 16;   // A: 2 thr/row, 16 bf16 each
    const int br = tid >> 3, blc = (tid & 7) * 16;   // B: 8 thr/row, 16 bf16 each
    const int aoff = ar * APAD + ka;
    const int boff = br * BPAD + blc;

    uint4 pah[2], pal[2], pbh[2], pbl[2];
    pah[0] = *(const uint4*)&Ah[(size_t)ar * NC + ka];
    pah[1] = *(const uint4*)&Ah[(size_t)ar * NC + ka + 8];
    pal[0] = *(const uint4*)&Al[(size_t)ar * NC + ka];
    pal[1] = *(const uint4*)&Al[(size_t)ar * NC + ka + 8];
    pbh[0] = *(const uint4*)&Bhb[(size_t)br * NL + blc];
    pbh[1] = *(const uint4*)&Bhb[(size_t)br * NL + blc + 8];
    pbl[0] = *(const uint4*)&Blb[(size_t)br * NL + blc];
    pbl[1] = *(const uint4*)&Blb[(size_t)br * NL + blc + 8];

    float acc[4][4][4];
#pragma unroll
    for (int i = 0; i < 4; i++)
#pragma unroll
        for (int j = 0; j < 4; j++)
#pragma unroll
            for (int r = 0; r < 4; r++) acc[i][j][r] = 0.f;

    const int a_row = wm * 64 + (lane & 15);
    const int a_col = (lane >> 4) * 8;
    const uint32_t aAh = cvta_smem(&sAh[a_row * APAD + a_col]);
    const uint32_t aAl = cvta_smem(&sAl[a_row * APAD + a_col]);
    const int b_row = (lane & 15);
    const int b_col = wn * 32 + (lane >> 4) * 8;
    const uint32_t aBh = cvta_smem(&sBh[b_row * BPAD + b_col]);
    const uint32_t aBl = cvta_smem(&sBl[b_row * BPAD + b_col]);

#pragma unroll 1
    for (int ch = 0; ch < 8; ch++) {
        const int q = ch & 1;
        const uint32_t qa = (uint32_t)(q * A_ELT * 2);
        const uint32_t qb = (uint32_t)(q * B_ELT * 2);
        *(uint4*)&sAh[q * A_ELT + aoff]      = pah[0];
        *(uint4*)&sAh[q * A_ELT + aoff + 8]  = pah[1];
        *(uint4*)&sAl[q * A_ELT + aoff]      = pal[0];
        *(uint4*)&sAl[q * A_ELT + aoff + 8]  = pal[1];
        *(uint4*)&sBh[q * B_ELT + boff]      = pbh[0];
        *(uint4*)&sBh[q * B_ELT + boff + 8]  = pbh[1];
        *(uint4*)&sBl[q * B_ELT + boff]      = pbl[0];
        *(uint4*)&sBl[q * B_ELT + boff + 8]  = pbl[1];
        __syncthreads();

        if (ch < 7) {
            const int k0 = (ch + 1) * 32;
            pah[0] = *(const uint4*)&Ah[(size_t)ar * NC + k0 + ka];
            pah[1] = *(const uint4*)&Ah[(size_t)ar * NC + k0 + ka + 8];
            pal[0] = *(const uint4*)&Al[(size_t)ar * NC + k0 + ka];
            pal[1] = *(const uint4*)&Al[(size_t)ar * NC + k0 + ka + 8];
            pbh[0] = *(const uint4*)&Bhb[(size_t)(k0 + br) * NL + blc];
            pbh[1] = *(const uint4*)&Bhb[(size_t)(k0 + br) * NL + blc + 8];
            pbl[0] = *(const uint4*)&Blb[(size_t)(k0 + br) * NL + blc];
            pbl[1] = *(const uint4*)&Blb[(size_t)(k0 + br) * NL + blc + 8];
        }

#pragma unroll
        for (int h = 0; h < 2; h++) {
            uint32_t bh[8], bl[8];
#pragma unroll
            for (int nt = 0; nt < 2; nt++) {
                const uint32_t off = (uint32_t)((h * 16) * BPAD + nt * 16) * 2;
                LDSM_X4_T(&bh[nt * 4], aBh + qb + off);
                LDSM_X4_T(&bl[nt * 4], aBl + qb + off);
            }
#pragma unroll
            for (int i = 0; i < 4; i++) {
                uint32_t ah[4], al[4];
                const uint32_t off = (uint32_t)((i * 16) * APAD + h * 16) * 2;
                LDSM_X4(ah, aAh + qa + off);
                LDSM_X4(al, aAl + qa + off);
#pragma unroll
                for (int j = 0; j < 4; j++) {
                    MMA_BF16(acc[i][j], ah, bh[j * 2], bh[j * 2 + 1]);
                    MMA_BF16(acc[i][j], ah, bl[j * 2], bl[j * 2 + 1]);
                    MMA_BF16(acc[i][j], al, bh[j * 2], bh[j * 2 + 1]);
                }
            }
        }
    }

    const int g   = lane >> 2;
    const int tig = lane & 3;
#pragma unroll
    for (int i = 0; i < 4; i++) {
        const int r0 = wm * 64 + i * 16 + g;
        const float bi0 = bi[r0];
        const float bi8 = bi[r0 + 8];
        OutT* y0 = Yb + (size_t)r0 * NL + wn * 32 + tig * 2;
        OutT* y8 = y0 + (size_t)8 * NL;
#pragma unroll
        for (int j = 0; j < 4; j++) {
            if (sizeof(OutT) == 2) {
                *(__half2*)&y0[j * 8] = __floats2half2_rn(acc[i][j][0] + bi0, acc[i][j][1] + bi0);
                *(__half2*)&y8[j * 8] = __floats2half2_rn(acc[i][j][2] + bi8, acc[i][j][3] + bi8);
            } else {
                *(float2*)&y0[j * 8] = make_float2(acc[i][j][0] + bi0, acc[i][j][1] + bi0);
                *(float2*)&y8[j * 8] = make_float2(acc[i][j][2] + bi8, acc[i][j][3] + bi8);
            }
        }
    }
}

// ---------------- BN stats (1024 thr, shuffle reduce) ----------------
__device__ __forceinline__ void warp_red2(float& s, float& s2)
{
#pragma unroll
    for (int o = 16; o > 0; o >>= 1) {
        s  += __shfl_xor_sync(0xFFFFFFFFu, s,  o);
        s2 += __shfl_xor_sync(0xFFFFFFFFu, s2, o);
    }
}

__global__ __launch_bounds__(1024) void bn_stats12_kernel(
    const float* __restrict__ g1, const float* __restrict__ be1,
    const float* __restrict__ g2, const float* __restrict__ be2)
{
    const int ch = blockIdx.x & (NC - 1);
    const bool first = blockIdx.x < NC;
    const __half* y = first ? g_y1h : g_y2h;
    float s = 0.f, s2 = 0.f;
#pragma unroll
    for (int k = 0; k < 2; k++) {
        const int i = (threadIdx.x + k * 1024) * 8;      // 8 halves per load
        const int b = i >> 12, l = i & (NL - 1);
        const uint4 u = *(const uint4*)&y[((size_t)b * NC + ch) * NL + l];
        const __half2* hp = (const __half2*)&u;
#pragma unroll
        for (int t = 0; t < 4; t++) {
            float2 f = __half22float2(hp[t]);
            s  += f.x + f.y;
            s2 += fmaf(f.x, f.x, f.y * f.y);
        }
    }
    warp_red2(s, s2);
    __shared__ float rs[32], rq[32];
    const int lane = threadIdx.x & 31, wid = threadIdx.x >> 5;
    if (lane == 0) { rs[wid] = s; rq[wid] = s2; }
    __syncthreads();
    if (wid == 0) {
        s = rs[lane]; s2 = rq[lane];
        warp_red2(s, s2);
        if (lane == 0) {
            const float inv = 1.f / (float)(NB * NL);
            float mu  = s * inv;
            float var = s2 * inv - mu * mu;
            float gwv = first ? g1[ch] : g2[ch];
            float bwv = first ? be1[ch] : be2[ch];
            float r   = rsqrtf(var + NEPS) * gwv;
            if (first) { g_sc1[ch] = r; g_sh1[ch] = bwv - mu * r; }
            else       { g_sc2[ch] = r; g_sh2[ch] = bwv - mu * r; }
        }
    }
}

__global__ __launch_bounds__(1024) void bn_statsF_relu_kernel(
    float* __restrict__ y,
    const float* __restrict__ gw, const float* __restrict__ bw)
{
    const int ch = blockIdx.x;
    float4 vv[4];
    size_t addr[4];
    float s = 0.f, s2 = 0.f;
#pragma unroll
    for (int k = 0; k < 4; k++) {
        const int i = (threadIdx.x + k * 1024) * 4;
        const int b = i >> 12, l = i & (NL - 1);
        addr[k] = ((size_t)b * NO + ch) * NL + l;
        float4 v = *(const float4*)&y[addr[k]];
        vv[k] = v;
        s  += (v.x + v.y) + (v.z + v.w);
        s2 += fmaf(v.x, v.x, v.y * v.y) + fmaf(v.z, v.z, v.w * v.w);
    }
    warp_red2(s, s2);
    __shared__ float rs[32], rq[32];
    __shared__ float bcast[2];
    const int lane = threadIdx.x & 31, wid = threadIdx.x >> 5;
    if (lane == 0) { rs[wid] = s; rq[wid] = s2; }
    __syncthreads();
    if (wid == 0) {
        s = rs[lane]; s2 = rq[lane];
        warp_red2(s, s2);
        if (lane == 0) {
            const float inv = 1.f / (float)(NB * NL);
            float mu  = s * inv;
            float var = s2 * inv - mu * mu;
            float r   = rsqrtf(var + NEPS) * gw[ch];
            bcast[0] = r;
            bcast[1] = bw[ch] - mu * r;
        }
    }
    __syncthreads();
    const float sc = bcast[0], sh = bcast[1];
#pragma unroll
    for (int k = 0; k < 4; k++) {
        float4 v = vv[k];
        v.x = fmaxf(fmaf(v.x, sc, sh), 0.f);
        v.y = fmaxf(fmaf(v.y, sc, sh), 0.f);
        v.z = fmaxf(fmaf(v.z, sc, sh), 0.f);
        v.w = fmaxf(fmaf(v.w, sc, sh), 0.f);
        *(float4*)&y[addr[k]] = v;
    }
}

// ---------------- scrambled-unfold attention ----------------------------------------
// Phase 1: two-base run decomposition. Within a group idx(l) is piecewise linear with
// one break at r = rc = 64-(l0&63) (row cross; plane cross coincides). So taps are
// base+r for r<rc, base2+r otherwise, with base2 = base + 2 (+C1-C0 if l0>=4088).
// One SEL + one imm-offset LDS.64 per tap; zero per-tap index math.
__global__ __launch_bounds__(ATT_THREADS, 1) void att_kernel(const float* __restrict__ x)
{
    extern __shared__ float sm[];
    float*  t12 = sm + ATT_F_T12;            // 66x66 interleaved (tri1, tri2) float2
    float*  xs  = sm + ATT_F_XS;             // 66x68 padded x plane (16B-aligned rows)
    __half* wsm = (__half*)(sm + ATT_F_WH);  // 36864 fp16 softmax weights

    const int bc = blockIdx.x;
    const int c  = bc & (NC - 1);
    const size_t base0 = (size_t)bc * NL;
    const float sc1 = g_sc1[c], sh1 = g_sh1[c];
    const float sc2 = g_sc2[c], sh2 = g_sh2[c];

    // zero ONLY the halo ring (260 cells per plane); interior is fully overwritten
    if (threadIdx.x < 260) {
        const int i = threadIdx.x;
        int r, col;
        if (i < 66)       { r = 0;       col = i; }
        else if (i < 132) { r = 65;      col = i - 66; }
        else if (i < 196) { r = i - 131; col = 0; }
        else              { r = i - 195; col = 65; }
        *(float2*)&t12[2 * (r * 66 + col)] = make_float2(0.f, 0.f);
        xs[r * 68 + col] = 0.f;
    }
    __syncthreads();

    {
        const int l4 = threadIdx.x * 4;      // exactly covers 0..4092
        float4 xv = *(const float4*)&x[base0 + l4];
        const __half2* ap = (const __half2*)(g_y1h + base0 + l4);
        const __half2* qp = (const __half2*)(g_y2h + base0 + l4);
        float2 a01 = __half22float2(ap[0]), a23 = __half22float2(ap[1]);
        float2 q01 = __half22float2(qp[0]), q23 = __half22float2(qp[1]);
        const int xidx = (l4 >> 6) * 68 + (l4 & 63) + 69;   // (row+1)*68 + col+1
        xs[xidx+0] = xv.x; xs[xidx+1] = xv.y; xs[xidx+2] = xv.z; xs[xidx+3] = xv.w;
        const int pidx = (l4 >> 6) * 66 + (l4 & 63) + 67;   // t12 keeps 66 pitch
        float t1v[4] = {
            fmaxf(fmaf(a01.x, sc1, sh1), 0.f), fmaxf(fmaf(a01.y, sc1, sh1), 0.f),
            fmaxf(fmaf(a23.x, sc1, sh1), 0.f), fmaxf(fmaf(a23.y, sc1, sh1), 0.f) };
        float t2v[4] = {
            fmaxf(fmaf(q01.x, sc2, sh2), 0.f), fmaxf(fmaf(q01.y, sc2, sh2), 0.f),
            fmaxf(fmaf(q23.x, sc2, sh2), 0.f), fmaxf(fmaf(q23.y, sc2, sh2), 0.f) };
#pragma unroll
        for (int j = 0; j < 4; j++)
            *(float2*)&t12[2 * (pidx + j)] = make_float2(t1v[j], t2v[j]);
    }
    __syncthreads();

    // phase 1: per group (9 consecutive n), emit the 9 softmax weights (fp16)
#pragma unroll
    for (int k = 0; k < 4; k++) {
        const int g  = threadIdx.x + k * ATT_THREADS;
        const int n0 = 9 * g;
        const int p0 = n0 >> 12;
        const int l0 = n0 & (NL - 1);
        const int di0 = (p0 * 171) >> 9, dj0 = p0 - 3 * di0;
        const int C0  = di0 * 66 + dj0;
        const int gb  = (l0 >> 6) * 66 + (l0 & 63) + C0;
        const int rc  = 64 - (l0 & 63);
        const int p1  = p0 + 1;
        const int di1 = (p1 * 171) >> 9, dj1 = p1 - 3 * di1;
        const int C1  = di1 * 66 + dj1 - 4224;
        const int adj = (l0 >= 4088) ? (2 + C1 - C0) : 2;
        const int gb2 = gb + adj;
        float ku[9], qu[9];
#pragma unroll
        for (int r = 0; r < 9; r++) {
            const int bs = (r < rc) ? gb : gb2;
            const float2 kq = *(const float2*)&t12[2 * (bs + r)];
            ku[r] = kq.x; qu[r] = kq.y;
        }
        const float quC = qu[4] * LOG2E;
        const float kuC = ku[4] * LOG2E;
        float e[9];
        float s = 0.f;
#pragma unroll
        for (int r = 0; r < 9; r++) {
            const float lg = fmaf(ku[r], quC, kuC * qu[r]);
            EX2_APPROX(e[r], lg);
            s += e[r];
        }
        const float inv = __fdividef(1.f, s);
#pragma unroll
        for (int r = 0; r < 9; r++)
            wsm[n0 + r] = __float2half_rn(e[r] * inv);
    }
    __syncthreads();

    // phase 2: weighted gather; xs taps via float4/float2, w via 8B fp16 loads
    {
        const int l4  = threadIdx.x * 4;
        const int row = l4 >> 6, col = l4 & 63;
        float acc[4] = {0.f, 0.f, 0.f, 0.f};
#pragma unroll
        for (int tr = 0; tr < 3; tr++) {
            const int pb = (row + tr) * 68 + col;     // 16B-aligned
            const float4 x03 = *(const float4*)&xs[pb];
            const float2 x45 = *(const float2*)&xs[pb + 4];
            const float xv[6] = {x03.x, x03.y, x03.z, x03.w, x45.x, x45.y};
#pragma unroll
            for (int dj = 0; dj < 3; dj++) {
                const int p = tr * 3 + dj;
                const uint2 wu = *(const uint2*)&wsm[(p << 12) + l4];
                const float2 w01 = __half22float2(*(const __half2*)&wu.x);
                const float2 w23 = __half22float2(*(const __half2*)&wu.y);
                acc[0] = fmaf(w01.x, xv[dj + 0], acc[0]);
                acc[1] = fmaf(w01.y, xv[dj + 1], acc[1]);
                acc[2] = fmaf(w23.x, xv[dj + 2], acc[2]);
                acc[3] = fmaf(w23.y, xv[dj + 3], acc[3]);
            }
        }
        uint32_t oh, ol, oh2, ol2;
        {
            __nv_bfloat16 h0 = __float2bfloat16(acc[0]);
            __nv_bfloat16 h1 = __float2bfloat16(acc[1]);
            __nv_bfloat16 l0b = __float2bfloat16(acc[0] - __bfloat162float(h0));
            __nv_bfloat16 l1b = __float2bfloat16(acc[1] - __bfloat162float(h1));
            __nv_bfloat162 ph = __halves2bfloat162(h0, h1);
            __nv_bfloat162 pl = __halves2bfloat162(l0b, l1b);
            oh = *(uint32_t*)&ph; ol = *(uint32_t*)&pl;
        }
        {
            __nv_bfloat16 h2 = __float2bfloat16(acc[2]);
            __nv_bfloat16 h3 = __float2bfloat16(acc[3]);
            __nv_bfloat16 l2b = __float2bfloat16(acc[2] - __bfloat162float(h2));
            __nv_bfloat16 l3b = __float2bfloat16(acc[3] - __bfloat162float(h3));
            __nv_bfloat162 ph = __halves2bfloat162(h2, h3);
            __nv_bfloat162 pl = __halves2bfloat162(l2b, l3b);
            oh2 = *(uint32_t*)&ph; ol2 = *(uint32_t*)&pl;
        }
        *(uint2*)&g_ph[base0 + l4] = make_uint2(oh, oh2);
        *(uint2*)&g_pl[base0 + l4] = make_uint2(ol, ol2);
    }
}

// ---------------- launch ----------------
extern "C" void kernel_launch(void* const* d_in, const int* in_sizes, int n_in,
                              void* d_out, int out_size)
{
    (void)in_sizes; (void)n_in; (void)out_size;
    const float* x   = (const float*)d_in[0];
    const float* w1  = (const float*)d_in[1];
    const float* b1  = (const float*)d_in[2];
    const float* g1  = (const float*)d_in[3];
    const float* be1 = (const float*)d_in[4];
    const float* w2  = (const float*)d_in[5];
    const float* b2  = (const float*)d_in[6];
    const float* g2  = (const float*)d_in[7];
    const float* be2 = (const float*)d_in[8];
    const float* wf  = (const float*)d_in[9];
    const float* bf  = (const float*)d_in[10];
    const float* gf  = (const float*)d_in[11];
    const float* bef = (const float*)d_in[12];
    float* out = (float*)d_out;

    cudaFuncSetAttribute(att_kernel, cudaFuncAttributeMaxDynamicSharedMemorySize,
                         ATT_SMEM_BYTES);
    cudaFuncSetAttribute(mma_gemm_kernel<__half>,
                         cudaFuncAttributeMaxDynamicSharedMemorySize, GEMM_SMEM_BYTES);
    cudaFuncSetAttribute(mma_gemm_kernel<float>,
                         cudaFuncAttributeMaxDynamicSharedMemorySize, GEMM_SMEM_BYTES);

    __half *y1p, *y2p;
    cudaGetSymbolAddress((void**)&y1p, g_y1h);
    cudaGetSymbolAddress((void**)&y2p, g_y2h);
    __nv_bfloat16 *xh, *xl, *ph, *pl, *wh, *wl, *wfh, *wfl;
    cudaGetSymbolAddress((void**)&xh,  g_xh);
    cudaGetSymbolAddress((void**)&xl,  g_xl);
    cudaGetSymbolAddress((void**)&ph,  g_ph);
    cudaGetSymbolAddress((void**)&pl,  g_pl);
    cudaGetSymbolAddress((void**)&wh,  g_wh);
    cudaGetSymbolAddress((void**)&wl,  g_wl);
    cudaGetSymbolAddress((void**)&wfh, g_wfh);
    cudaGetSymbolAddress((void**)&wfl, g_wfl);

    conv_all_kernel<<<CONV_X_BLOCKS + CONV_W_BLOCKS, 256>>>(x, w1, w2, wf);

    // dual GEMM: stacked M=512 (rows 0-255 -> w1/y1, 256-511 -> w2/y2), fp16 out
    dim3 gd(4, NL / 128, NB);
    mma_gemm_kernel<__half><<<gd, 256, GEMM_SMEM_BYTES>>>(
        wh, wl, wh + NC * NC, wl + NC * NC, b1, b2, xh, xl, y1p, y2p, 256);
    bn_stats12_kernel<<<2 * NC, 1024>>>(g1, be1, g2, be2);
    att_kernel<<<NB * NC, ATT_THREADS, ATT_SMEM_BYTES>>>(x);
    // final GEMM: M=256 single matrix, fp32 out
    dim3 gf2(2, NL / 128, NB);
    mma_gemm_kernel<float><<<gf2, 256, GEMM_SMEM_BYTES>>>(
        wfh, wfl, wfh, wfl, bf, bf, ph, pl, out, out, 512);
    bn_statsF_relu_kernel<<<NO, 1024>>>(out, gf, bef);
}